// round 9
// baseline (speedup 1.0000x reference)
#include <cuda_runtime.h>
#include <cuda_bf16.h>
#include <math.h>
#include <stdint.h>

#define B_   512
#define T_   1005
#define E_   100
#define L_   10
#define N_   20
#define V_   32000
#define NCH  100      // n_full = T/L
#define REST 5        // T % L

// ---- scratch (no allocations allowed) ----
__device__ float g_h[B_ * N_ * E_];       // final h
__device__ float g_ya[B_ * E_];           // prelu(y)

// ---- packed fp32x2 helpers (out_kernel) ----
__device__ __forceinline__ unsigned long long lds2(const float* p) {
    return *reinterpret_cast<const unsigned long long*>(p);
}
__device__ __forceinline__ void ffma2(unsigned long long& d,
                                      unsigned long long a,
                                      unsigned long long b) {
    asm("fma.rn.f32x2 %0, %1, %2, %0;" : "+l"(d) : "l"(a), "l"(b));
}
__device__ __forceinline__ float hadd2(unsigned long long v) {
    float lo, hi;
    asm("mov.b64 {%0, %1}, %2;" : "=f"(lo), "=f"(hi) : "l"(v));
    return lo + hi;
}

// ---- warp MMA helpers (portable PTX, sm_80+) ----
__device__ __forceinline__ uint32_t smem_u32(const void* p) {
    uint32_t a;
    asm("{ .reg .u64 t; cvta.to.shared.u64 t, %1; cvt.u32.u64 %0, t; }"
        : "=r"(a) : "l"(p));
    return a;
}
__device__ __forceinline__ void ldsm4(uint32_t* r, uint32_t a) {
    asm volatile("ldmatrix.sync.aligned.m8n8.x4.shared.b16 {%0,%1,%2,%3}, [%4];"
        : "=r"(r[0]), "=r"(r[1]), "=r"(r[2]), "=r"(r[3]) : "r"(a));
}
__device__ __forceinline__ void ldsm2(uint32_t* r, uint32_t a) {
    asm volatile("ldmatrix.sync.aligned.m8n8.x2.shared.b16 {%0,%1}, [%2];"
        : "=r"(r[0]), "=r"(r[1]) : "r"(a));
}
__device__ __forceinline__ void mma16816(float* c, const uint32_t* a, const uint32_t* b) {
    asm volatile(
        "mma.sync.aligned.m16n8k16.row.col.f32.bf16.bf16.f32 "
        "{%0,%1,%2,%3}, {%4,%5,%6,%7}, {%8,%9}, {%0,%1,%2,%3};"
        : "+f"(c[0]), "+f"(c[1]), "+f"(c[2]), "+f"(c[3])
        : "r"(a[0]), "r"(a[1]), "r"(a[2]), "r"(a[3]), "r"(b[0]), "r"(b[1]));
}
// split two fp32 into packed bf16 hi + residual lo
__device__ __forceinline__ void split2(float x0, float x1, uint32_t& hi, uint32_t& lo) {
    __nv_bfloat162 bh = __floats2bfloat162_rn(x0, x1);
    uint32_t h = *reinterpret_cast<uint32_t*>(&bh);
    float hf0 = __uint_as_float(h << 16);
    float hf1 = __uint_as_float(h & 0xffff0000u);
    __nv_bfloat162 bl = __floats2bfloat162_rn(x0 - hf0, x1 - hf1);
    hi = h;
    lo = *reinterpret_cast<uint32_t*>(&bl);
}

// ============================================================
// K2: persistent scan on warp MMA (bf16x3). 128 CTAs x 4 batches.
//     6 MMA warps (m32 x n56 each) + 10 helper warps.
// ============================================================
#define NB   4
#define NTH  512
#define BST  240      // byte stride of bf16 tile rows (15*16B, LDSM conflict-free)
#define HST  108      // float stride of sH rows
#define SST  104      // float stride of small arrays

#define A_HILO 23040                       // 96*240
#define B_HILO 26880                       // 112*240
#define OFF_AHI 0                          // 23040
#define OFF_ALO 23040                      // 23040
#define OFF_BHI 46080                      // 26880
#define OFF_BLO 72960                      // 26880
#define OFF_H   99840                      // 80*108*4 = 34560
#define OFF_W   134400                     // 100*100*4 = 40000
#define OFF_WM  174400                     // 20*104*4 = 8320
#define OFF_VW  182720                     // 8320
#define OFF_S   191040                     // 2*4*104*4 = 3328
#define OFF_SSW 194368                     // 4*104*4 = 1664
#define OFF_G   196032                     // 320
#define OFF_GP  196352                     // 640
#define OFF_F   196992                     // 10*100*4 = 4000
#define SCAN_SMEM 200992

__global__ __launch_bounds__(NTH, 1) void scan_mma_kernel(
    const float* __restrict__ U_w, const float* __restrict__ V_w,
    const float* __restrict__ W_w, const float* __restrict__ w_mem,
    const float* __restrict__ h0,  const float* __restrict__ a_dm_p,
    const float* __restrict__ in_data, const float* __restrict__ f_w)
{
    extern __shared__ char smc[];
    float* sH  = (float*)(smc + OFF_H);
    float* sW  = (float*)(smc + OFF_W);
    float* sWm = (float*)(smc + OFF_WM);
    float* sVw = (float*)(smc + OFF_VW);
    float* sS  = (float*)(smc + OFF_S);
    float* sSW = (float*)(smc + OFF_SSW);
    float* sG  = (float*)(smc + OFF_G);
    float* sGp = (float*)(smc + OFF_GP);
    float* sF  = (float*)(smc + OFF_F);

    const int tid = threadIdx.x;
    const int w = tid >> 5;
    const int lane = tid & 31;
    const int b0g = blockIdx.x * NB;
    const float adm = *a_dm_p;
    const uint32_t smb = smem_u32(smc);

    // ---- zero A+B tiles (pad rows/cols must stay zero) ----
    for (int i = tid; i < OFF_H / 4; i += NTH) ((uint32_t*)smc)[i] = 0;
    __syncthreads();

    // ---- stage U (bf16 hi/lo), W, w_mem, f, h init + A tiles from h0 ----
    for (int i = tid; i < E_ * 50; i += NTH) {
        int f_ = i / 50, p = i % 50;
        float2 uv = *(const float2*)(U_w + f_ * E_ + 2 * p);
        uint32_t hi, lo;
        split2(uv.x, uv.y, hi, lo);
        *(uint32_t*)(smc + OFF_BHI + f_ * BST + p * 4) = hi;
        *(uint32_t*)(smc + OFF_BLO + f_ * BST + p * 4) = lo;
    }
    for (int i = tid; i < E_ * E_; i += NTH) sW[i] = W_w[i];
    for (int i = tid; i < L_ * E_; i += NTH) sF[i] = f_w[i];
    for (int i = tid; i < N_ * E_; i += NTH) {
        int n_ = i / E_, e_ = i % E_;
        sWm[n_ * SST + e_] = w_mem[i];
    }
    for (int i = tid; i < 80 * 50; i += NTH) {
        int row = i / 50, p = i % 50;
        float2 hv = *(const float2*)(h0 + (row % N_) * E_ + 2 * p);
        *(float2*)(sH + row * HST + 2 * p) = hv;
        uint32_t hi, lo;
        split2(hv.x, hv.y, hi, lo);
        *(uint32_t*)(smc + OFF_AHI + row * BST + p * 4) = hi;
        *(uint32_t*)(smc + OFF_ALO + row * BST + p * 4) = lo;
    }
    if (tid < 80) { sGp[2 * tid] = 1.f; sGp[2 * tid + 1] = 0.f; }
    __syncthreads();
    // Vw[n][f] = w_mem[n] . V_w[f] (one-time)
    for (int i = tid; i < N_ * E_; i += NTH) {
        int n_ = i / E_, f_ = i % E_;
        float acc = 0.f;
        for (int e_ = 0; e_ < E_; e_++) acc += sWm[n_ * SST + e_] * V_w[f_ * E_ + e_];
        sVw[n_ * SST + f_] = acc;
    }
    // s_0 = infos(t=0) computed in place
    for (int i = tid; i < NB * E_; i += NTH) {
        int bi = i / E_, e_ = i % E_;
        const float* ip = in_data + (long)(b0g + bi) * T_ * E_ + e_;
        float acc = 0.f;
#pragma unroll
        for (int l = 0; l < L_; l++) acc += sF[l * E_ + e_] * ip[(long)l * E_];
        sS[bi * SST + e_] = acc;
    }
    __syncthreads();

    // MMA warp geometry: 6 warps, w = mg*2 + nh; m32 x n56 per warp
    const int mg = w >> 1, nh = w & 1;
    const int m0 = mg * 32;
    const int qr = lane >> 2, qc = lane & 3;
    const int grp = lane >> 3, lr = lane & 7;

    for (int t = 0; t < NCH; t++) {
        const float* sScur = sS + (t & 1) * NB * SST;

        // ================= phase A =================
        float acc[2][7][4];
        float invA[2], invB[2];
        if (w < 6) {
#pragma unroll
            for (int mh = 0; mh < 2; mh++) {
                int ra = m0 + 16 * mh + qr;
                int rb = ra + 8;
                invA[mh] = (ra < 80) ? rsqrtf(sGp[2 * ra] + sGp[2 * ra + 1]) : 1.f;
                invB[mh] = (rb < 80) ? rsqrtf(sGp[2 * rb] + sGp[2 * rb + 1]) : 1.f;
            }
#pragma unroll
            for (int mh = 0; mh < 2; mh++)
#pragma unroll
                for (int j = 0; j < 7; j++)
#pragma unroll
                    for (int q = 0; q < 4; q++) acc[mh][j][q] = 0.f;
            const uint32_t aBase = smb + OFF_AHI;
            const uint32_t bhBase = smb + OFF_BHI;
#pragma unroll
            for (int k = 0; k < 7; k++) {
                uint32_t ah[2][4], al[2][4];
#pragma unroll
                for (int mh = 0; mh < 2; mh++) {
                    uint32_t aaddr = aBase + (uint32_t)((m0 + 16 * mh + lr + ((grp & 1) << 3)) * BST
                                   + k * 32 + ((grp >> 1) << 4));
                    ldsm4(ah[mh], aaddr);
                    ldsm4(al[mh], aaddr + (uint32_t)A_HILO);
                }
#pragma unroll
                for (int pq = 0; pq < 3; pq++) {
                    int t0 = nh * 7 + pq * 2;
                    uint32_t addr = bhBase + (uint32_t)((t0 * 8 + lr + (grp >> 1) * 8) * BST
                                  + k * 32 + (grp & 1) * 16);
                    uint32_t bh[4], bl[4];
                    ldsm4(bh, addr);
                    ldsm4(bl, addr + (uint32_t)B_HILO);
#pragma unroll
                    for (int mh = 0; mh < 2; mh++)
#pragma unroll
                        for (int jj = 0; jj < 2; jj++) {
                            int j = pq * 2 + jj;
                            mma16816(acc[mh][j], ah[mh], &bh[2 * jj]);
                            mma16816(acc[mh][j], al[mh], &bh[2 * jj]);
                            mma16816(acc[mh][j], ah[mh], &bl[2 * jj]);
                        }
                }
                {   // tail tile (j=6)
                    int t6 = nh * 7 + 6;
                    uint32_t addr = bhBase + (uint32_t)((t6 * 8 + lr) * BST
                                  + k * 32 + ((lane >> 3) & 1) * 16);
                    uint32_t bh[2], bl[2];
                    ldsm2(bh, addr);
                    ldsm2(bl, addr + (uint32_t)B_HILO);
#pragma unroll
                    for (int mh = 0; mh < 2; mh++) {
                        mma16816(acc[mh][6], ah[mh], bh);
                        mma16816(acc[mh][6], al[mh], bh);
                        mma16816(acc[mh][6], ah[mh], bl);
                    }
                }
            }
        } else {
            int i0 = tid - 192;   // 0..319
            // ---- early-issue LDGs for s_{t+1} ----
            float v0[10], v1[10];
            int bi0 = i0 / E_, e0 = i0 % E_;
            int i1 = i0 + 320;
            int bi1 = i1 / E_, e1 = i1 % E_;
            bool h1 = (i1 < NB * E_);
            if (t + 1 < NCH) {
                const float* ip0 = in_data + ((long)(b0g + bi0) * T_ + (t + 1) * L_) * E_ + e0;
#pragma unroll
                for (int l = 0; l < L_; l++) v0[l] = ip0[(long)l * E_];
                if (h1) {
                    const float* ip1 = in_data + ((long)(b0g + bi1) * T_ + (t + 1) * L_) * E_ + e1;
#pragma unroll
                    for (int l = 0; l < L_; l++) v1[l] = ip1[(long)l * E_];
                }
            }
            // ---- sSW / gate (overlaps LDG latency) ----
            if (i0 < 100) {
                int f_ = i0;
                float a0 = 0.f, a1 = 0.f, a2 = 0.f, a3 = 0.f;
                const float* wp = sW + f_ * E_;
                for (int e4 = 0; e4 < 25; e4++) {
                    float4 wv = *(const float4*)(wp + e4 * 4);
                    float4 s0 = *(const float4*)(sScur + 0 * SST + e4 * 4);
                    float4 s1 = *(const float4*)(sScur + 1 * SST + e4 * 4);
                    float4 s2 = *(const float4*)(sScur + 2 * SST + e4 * 4);
                    float4 s3 = *(const float4*)(sScur + 3 * SST + e4 * 4);
                    a0 += wv.x * s0.x + wv.y * s0.y + wv.z * s0.z + wv.w * s0.w;
                    a1 += wv.x * s1.x + wv.y * s1.y + wv.z * s1.z + wv.w * s1.w;
                    a2 += wv.x * s2.x + wv.y * s2.y + wv.z * s2.z + wv.w * s2.w;
                    a3 += wv.x * s3.x + wv.y * s3.y + wv.z * s3.z + wv.w * s3.w;
                }
                sSW[0 * SST + f_] = a0;
                sSW[1 * SST + f_] = a1;
                sSW[2 * SST + f_] = a2;
                sSW[3 * SST + f_] = a3;
            } else if (i0 < 180) {
                int row = i0 - 100;
                int bi = row / N_, ne = row % N_;
                const float* hp = sH + row * HST;
                const float* wp = sWm + ne * SST;
                const float* sp = sScur + bi * SST;
                float hs = 0.f, ws = 0.f;
                for (int e4 = 0; e4 < 25; e4++) {
                    float4 hv = *(const float4*)(hp + e4 * 4);
                    float4 wv = *(const float4*)(wp + e4 * 4);
                    float4 sv = *(const float4*)(sp + e4 * 4);
                    hs += hv.x * sv.x + hv.y * sv.y + hv.z * sv.z + hv.w * sv.w;
                    ws += wv.x * sv.x + wv.y * sv.y + wv.z * sv.z + wv.w * sv.w;
                }
                float inv = rsqrtf(sGp[2 * row] + sGp[2 * row + 1]);
                sG[row] = 1.f / (1.f + expf(-(inv * hs + ws)));
            }
            // ---- combine + store s_{t+1} ----
            if (t + 1 < NCH) {
                float* sNxt = sS + ((t + 1) & 1) * NB * SST;
                float a = 0.f;
#pragma unroll
                for (int l = 0; l < L_; l++) a += sF[l * E_ + e0] * v0[l];
                sNxt[bi0 * SST + e0] = a;
                if (h1) {
                    float b = 0.f;
#pragma unroll
                    for (int l = 0; l < L_; l++) b += sF[l * E_ + e1] * v1[l];
                    sNxt[bi1 * SST + e1] = b;
                }
            }
        }
        __syncthreads();

        // ================= phase B: epilogue + A-tile store =================
        if (w < 6) {
#pragma unroll
            for (int mh = 0; mh < 2; mh++) {
                if (m0 + 16 * mh >= 80) continue;
                int r0 = m0 + 16 * mh + qr, r1 = r0 + 8;
                float iA = invA[mh], iB = invB[mh];
                float g0 = sG[r0], g1 = sG[r1];
                int bi0 = r0 / N_, ne0 = r0 % N_;
                int bi1 = r1 / N_, ne1 = r1 % N_;
                float ssq0 = 0.f, ssq1 = 0.f;
#pragma unroll
                for (int j = 0; j < 7; j++) {
                    int f0 = (nh * 7 + j) * 8 + 2 * qc;
                    if (f0 < 100) {
                        float2 vw0 = *(const float2*)(sVw + ne0 * SST + f0);
                        float2 sw0 = *(const float2*)(sSW + bi0 * SST + f0);
                        float2 hv0 = *(const float2*)(sH + r0 * HST + f0);
                        float c0 = acc[mh][j][0] * iA + vw0.x + sw0.x;
                        float c1 = acc[mh][j][1] * iA + vw0.y + sw0.y;
                        c0 = (c0 >= 0.f) ? c0 : adm * c0;
                        c1 = (c1 >= 0.f) ? c1 : adm * c1;
                        float n0v = hv0.x * iA + g0 * c0;
                        float n1v = hv0.y * iA + g0 * c1;
                        *(float2*)(sH + r0 * HST + f0) = make_float2(n0v, n1v);
                        ssq0 += n0v * n0v + n1v * n1v;
                        uint32_t hi0, lo0;
                        split2(n0v, n1v, hi0, lo0);
                        *(uint32_t*)(smc + OFF_AHI + r0 * BST + f0 * 2) = hi0;
                        *(uint32_t*)(smc + OFF_ALO + r0 * BST + f0 * 2) = lo0;

                        float2 vw1 = *(const float2*)(sVw + ne1 * SST + f0);
                        float2 sw1 = *(const float2*)(sSW + bi1 * SST + f0);
                        float2 hv1 = *(const float2*)(sH + r1 * HST + f0);
                        float d0 = acc[mh][j][2] * iB + vw1.x + sw1.x;
                        float d1 = acc[mh][j][3] * iB + vw1.y + sw1.y;
                        d0 = (d0 >= 0.f) ? d0 : adm * d0;
                        d1 = (d1 >= 0.f) ? d1 : adm * d1;
                        float m0v = hv1.x * iB + g1 * d0;
                        float m1v = hv1.y * iB + g1 * d1;
                        *(float2*)(sH + r1 * HST + f0) = make_float2(m0v, m1v);
                        ssq1 += m0v * m0v + m1v * m1v;
                        uint32_t hi1, lo1;
                        split2(m0v, m1v, hi1, lo1);
                        *(uint32_t*)(smc + OFF_AHI + r1 * BST + f0 * 2) = hi1;
                        *(uint32_t*)(smc + OFF_ALO + r1 * BST + f0 * 2) = lo1;
                    }
                }
                ssq0 += __shfl_xor_sync(0xffffffffu, ssq0, 1);
                ssq0 += __shfl_xor_sync(0xffffffffu, ssq0, 2);
                ssq1 += __shfl_xor_sync(0xffffffffu, ssq1, 1);
                ssq1 += __shfl_xor_sync(0xffffffffu, ssq1, 2);
                if (qc == 0) {
                    sGp[2 * r0 + nh] = ssq0;
                    sGp[2 * r1 + nh] = ssq1;
                }
            }
        }
        __syncthreads();
    }

    // ---- final normalize + write h ----
    for (int i = tid; i < 80 * E_; i += NTH) {
        int row = i / E_, e_ = i % E_;
        float inv = rsqrtf(sGp[2 * row] + sGp[2 * row + 1]);
        g_h[(long)(b0g + row / N_) * N_ * E_ + (row % N_) * E_ + e_] =
            sH[row * HST + e_] * inv;
    }
}

// ============================================================
// K3: attention over entities + hidden head, per batch
//     (q projection from tail tokens fused in)
// ============================================================
__global__ void attn_kernel(const float* __restrict__ H_w,
                            const float* __restrict__ H_b,
                            const float* __restrict__ a_out_p,
                            const float* __restrict__ in_data,
                            const float* __restrict__ f_w) {
    __shared__ float sh[N_ * E_];
    __shared__ float sq[E_];
    __shared__ float sl[N_];
    __shared__ float sp[N_];
    __shared__ float su[E_];
    int b = blockIdx.x, tid = threadIdx.x;
    for (int i = tid; i < N_ * E_; i += 128) sh[i] = g_h[b * N_ * E_ + i];
    if (tid < E_) {
        const float* ip = in_data + ((long)b * T_ + NCH * L_) * E_ + tid;
        float acc = 0.f;
#pragma unroll
        for (int l = 0; l < REST; l++) acc += f_w[l * E_ + tid] * ip[(long)l * E_];
        sq[tid] = acc;
    }
    __syncthreads();
    if (tid < N_) {
        float acc = 0.f;
        for (int e = 0; e < E_; e++) acc += sh[tid * E_ + e] * sq[e];
        sl[tid] = acc;
    }
    __syncthreads();
    if (tid == 0) {
        float m = sl[0];
        for (int n = 1; n < N_; n++) m = fmaxf(m, sl[n]);
        float s = 0.f;
        for (int n = 0; n < N_; n++) { float ev = expf(sl[n] - m); sp[n] = ev; s += ev; }
        float inv = 1.f / s;
        for (int n = 0; n < N_; n++) sp[n] *= inv;
    }
    __syncthreads();
    if (tid < E_) {
        float u = 0.f;
        for (int n = 0; n < N_; n++) u += sp[n] * sh[n * E_ + tid];
        su[tid] = u;
    }
    __syncthreads();
    if (tid < E_) {
        int f_ = tid;
        float acc = sq[f_] + H_b[f_];
        for (int e = 0; e < E_; e++) acc += su[e] * H_w[f_ * E_ + e];
        float ao = *a_out_p;
        g_ya[b * E_ + f_] = (acc >= 0.f) ? acc : ao * acc;
    }
}

// ============================================================
// K4: out[b][v] = ya[b] . R_w[v] + R_b[v]  (512 x 32000, K=100)
//     128x64 tiles, FFMA2.
// ============================================================
#define NP 50
#define K4_SMEM_FLOATS (128*NP*2 + 64*NP*2)
__global__ __launch_bounds__(256) void out_kernel(const float* __restrict__ R_w,
                                                  const float* __restrict__ R_b,
                                                  float* __restrict__ out) {
    extern __shared__ float osm[];
    float* sA2 = osm;                 // [p][bi] pairs, 128 rows
    float* sB2 = osm + 128 * NP * 2;  // [p][vi] pairs, 64 cols
    int tid = threadIdx.x;
    int v0 = blockIdx.x * 64, b0 = blockIdx.y * 128;
    for (int i = tid; i < 128 * NP; i += 256) {
        int bi = i / NP, p = i % NP;
        float2 v = *(const float2*)(g_ya + (long)(b0 + bi) * E_ + 2 * p);
        sA2[(p * 128 + bi) * 2]     = v.x;
        sA2[(p * 128 + bi) * 2 + 1] = v.y;
    }
    for (int i = tid; i < 64 * NP; i += 256) {
        int vi = i / NP, p = i % NP;
        float2 v = *(const float2*)(R_w + (long)(v0 + vi) * E_ + 2 * p);
        sB2[(p * 64 + vi) * 2]     = v.x;
        sB2[(p * 64 + vi) * 2 + 1] = v.y;
    }
    __syncthreads();
    int bi8 = (tid >> 4) << 3;    // rows bi8..bi8+7
    int vj  = tid & 15;           // cols {vj, vj+16, vj+32, vj+48}
    unsigned long long acc2[8][4];
#pragma unroll
    for (int k = 0; k < 8; k++)
#pragma unroll
        for (int j = 0; j < 4; j++) acc2[k][j] = 0ull;
#pragma unroll 2
    for (int p = 0; p < NP; p++) {
        unsigned long long a2[8], b2[4];
#pragma unroll
        for (int j = 0; j < 4; j++) b2[j] = lds2(sB2 + (p * 64 + vj + 16 * j) * 2);
#pragma unroll
        for (int k = 0; k < 8; k++) a2[k] = lds2(sA2 + (p * 128 + bi8 + k) * 2);
#pragma unroll
        for (int k = 0; k < 8; k++)
#pragma unroll
            for (int j = 0; j < 4; j++) ffma2(acc2[k][j], a2[k], b2[j]);
    }
    float rb[4];
#pragma unroll
    for (int j = 0; j < 4; j++) rb[j] = R_b[v0 + vj + 16 * j];
#pragma unroll
    for (int k = 0; k < 8; k++) {
#pragma unroll
        for (int j = 0; j < 4; j++) {
            out[(long)(b0 + bi8 + k) * V_ + v0 + vj + 16 * j] = hadd2(acc2[k][j]) + rb[j];
        }
    }
}

// ============================================================
extern "C" void kernel_launch(void* const* d_in, const int* in_sizes, int n_in,
                              void* d_out, int out_size) {
    const float* in_data = (const float*)d_in[0];
    const float* f       = (const float*)d_in[1];
    const float* h0      = (const float*)d_in[2];
    const float* w_mem   = (const float*)d_in[3];
    const float* U_w     = (const float*)d_in[4];
    const float* V_w     = (const float*)d_in[5];
    const float* W_w     = (const float*)d_in[6];
    const float* a_dm    = (const float*)d_in[7];
    const float* H_w     = (const float*)d_in[8];
    const float* H_b     = (const float*)d_in[9];
    const float* R_w     = (const float*)d_in[10];
    const float* R_b     = (const float*)d_in[11];
    const float* a_out   = (const float*)d_in[12];
    float* out = (float*)d_out;

    cudaFuncSetAttribute(scan_mma_kernel, cudaFuncAttributeMaxDynamicSharedMemorySize,
                         SCAN_SMEM);
    const int k4_smem = K4_SMEM_FLOATS * (int)sizeof(float);
    cudaFuncSetAttribute(out_kernel, cudaFuncAttributeMaxDynamicSharedMemorySize,
                         k4_smem);

    scan_mma_kernel<<<B_ / NB, NTH, SCAN_SMEM>>>(U_w, V_w, W_w, w_mem, h0, a_dm,
                                                 in_data, f);
    attn_kernel<<<B_, 128>>>(H_w, H_b, a_out, in_data, f);
    dim3 g4(V_ / 64, B_ / 128);
    out_kernel<<<g4, 256, k4_smem>>>(R_w, R_b, out);
}

// round 10
// speedup vs baseline: 1.1713x; 1.1713x over previous
#include <cuda_runtime.h>
#include <cuda_bf16.h>
#include <math.h>
#include <stdint.h>

#define B_   512
#define T_   1005
#define E_   100
#define L_   10
#define N_   20
#define V_   32000
#define NCH  100      // n_full = T/L
#define REST 5        // T % L

// ---- scratch (no allocations allowed) ----
__device__ float g_ya[B_ * E_];           // prelu(y)

// ---- packed fp32x2 helpers (out_kernel) ----
__device__ __forceinline__ unsigned long long lds2(const float* p) {
    return *reinterpret_cast<const unsigned long long*>(p);
}
__device__ __forceinline__ void ffma2(unsigned long long& d,
                                      unsigned long long a,
                                      unsigned long long b) {
    asm("fma.rn.f32x2 %0, %1, %2, %0;" : "+l"(d) : "l"(a), "l"(b));
}
__device__ __forceinline__ float hadd2(unsigned long long v) {
    float lo, hi;
    asm("mov.b64 {%0, %1}, %2;" : "=f"(lo), "=f"(hi) : "l"(v));
    return lo + hi;
}

// ---- warp MMA helpers (portable PTX, sm_80+) ----
__device__ __forceinline__ uint32_t smem_u32(const void* p) {
    uint32_t a;
    asm("{ .reg .u64 t; cvta.to.shared.u64 t, %1; cvt.u32.u64 %0, t; }"
        : "=r"(a) : "l"(p));
    return a;
}
__device__ __forceinline__ void ldsm4(uint32_t* r, uint32_t a) {
    asm volatile("ldmatrix.sync.aligned.m8n8.x4.shared.b16 {%0,%1,%2,%3}, [%4];"
        : "=r"(r[0]), "=r"(r[1]), "=r"(r[2]), "=r"(r[3]) : "r"(a));
}
__device__ __forceinline__ void ldsm2(uint32_t* r, uint32_t a) {
    asm volatile("ldmatrix.sync.aligned.m8n8.x2.shared.b16 {%0,%1}, [%2];"
        : "=r"(r[0]), "=r"(r[1]) : "r"(a));
}
__device__ __forceinline__ void mma16816(float* c, const uint32_t* a, const uint32_t* b) {
    asm volatile(
        "mma.sync.aligned.m16n8k16.row.col.f32.bf16.bf16.f32 "
        "{%0,%1,%2,%3}, {%4,%5,%6,%7}, {%8,%9}, {%0,%1,%2,%3};"
        : "+f"(c[0]), "+f"(c[1]), "+f"(c[2]), "+f"(c[3])
        : "r"(a[0]), "r"(a[1]), "r"(a[2]), "r"(a[3]), "r"(b[0]), "r"(b[1]));
}
// split two fp32 into packed bf16 hi + residual lo
__device__ __forceinline__ void split2(float x0, float x1, uint32_t& hi, uint32_t& lo) {
    __nv_bfloat162 bh = __floats2bfloat162_rn(x0, x1);
    uint32_t h = *reinterpret_cast<uint32_t*>(&bh);
    float hf0 = __uint_as_float(h << 16);
    float hf1 = __uint_as_float(h & 0xffff0000u);
    __nv_bfloat162 bl = __floats2bfloat162_rn(x0 - hf0, x1 - hf1);
    hi = h;
    lo = *reinterpret_cast<uint32_t*>(&bl);
}

// ============================================================
// K2: persistent scan on warp MMA (bf16x3). 128 CTAs x 4 batches.
//     10 MMA warps + 6 helper warps; infos fused (hoisted LDGs);
//     attention + head fused at the tail.
// ============================================================
#define NB   4
#define NTH  512
#define BST  240      // byte stride of bf16 tile rows (15*16B, LDSM conflict-free)
#define HST  108      // float stride of sH rows
#define SST  104      // float stride of small arrays

#define OFF_AHI 0                          // 80*240  = 19200
#define OFF_ALO 19200                      // 19200
#define OFF_BHI 38400                      // 112*240 = 26880
#define OFF_BLO 65280                      // 26880
#define OFF_H   92160                      // 80*108*4 = 34560
#define OFF_W   126720                     // 100*100*4 = 40000
#define OFF_WM  166720                     // 20*104*4 = 8320
#define OFF_VW  175040                     // 8320
#define OFF_S   183360                     // 2*4*104*4 = 3328
#define OFF_SSW 186688                     // 4*104*4 = 1664
#define OFF_G   188352                     // 320
#define OFF_GP  188672                     // 640
#define OFF_F   189312                     // 10*100*4 = 4000
#define SCAN_SMEM 193312

__global__ __launch_bounds__(NTH, 1) void scan_mma_kernel(
    const float* __restrict__ U_w, const float* __restrict__ V_w,
    const float* __restrict__ W_w, const float* __restrict__ w_mem,
    const float* __restrict__ h0,  const float* __restrict__ a_dm_p,
    const float* __restrict__ in_data, const float* __restrict__ f_w,
    const float* __restrict__ H_w, const float* __restrict__ H_b,
    const float* __restrict__ a_out_p)
{
    extern __shared__ char smc[];
    float* sH  = (float*)(smc + OFF_H);
    float* sW  = (float*)(smc + OFF_W);
    float* sWm = (float*)(smc + OFF_WM);
    float* sVw = (float*)(smc + OFF_VW);
    float* sS  = (float*)(smc + OFF_S);
    float* sSW = (float*)(smc + OFF_SSW);
    float* sG  = (float*)(smc + OFF_G);
    float* sGp = (float*)(smc + OFF_GP);
    float* sF  = (float*)(smc + OFF_F);

    const int tid = threadIdx.x;
    const int w = tid >> 5;
    const int lane = tid & 31;
    const int b0g = blockIdx.x * NB;
    const float adm = *a_dm_p;
    const uint32_t smb = smem_u32(smc);

    // ---- zero A+B tiles (pad rows/cols must stay zero) ----
    for (int i = tid; i < OFF_H / 4; i += NTH) ((uint32_t*)smc)[i] = 0;
    __syncthreads();

    // ---- stage U (bf16 hi/lo), W, w_mem, f, h init + A tiles from h0 ----
    for (int i = tid; i < E_ * 50; i += NTH) {
        int f_ = i / 50, p = i % 50;
        float2 uv = *(const float2*)(U_w + f_ * E_ + 2 * p);
        uint32_t hi, lo;
        split2(uv.x, uv.y, hi, lo);
        *(uint32_t*)(smc + OFF_BHI + f_ * BST + p * 4) = hi;
        *(uint32_t*)(smc + OFF_BLO + f_ * BST + p * 4) = lo;
    }
    for (int i = tid; i < E_ * E_; i += NTH) sW[i] = W_w[i];
    for (int i = tid; i < L_ * E_; i += NTH) sF[i] = f_w[i];
    for (int i = tid; i < N_ * E_; i += NTH) {
        int n_ = i / E_, e_ = i % E_;
        sWm[n_ * SST + e_] = w_mem[i];
    }
    for (int i = tid; i < 80 * 50; i += NTH) {
        int row = i / 50, p = i % 50;
        float2 hv = *(const float2*)(h0 + (row % N_) * E_ + 2 * p);
        *(float2*)(sH + row * HST + 2 * p) = hv;
        uint32_t hi, lo;
        split2(hv.x, hv.y, hi, lo);
        *(uint32_t*)(smc + OFF_AHI + row * BST + p * 4) = hi;
        *(uint32_t*)(smc + OFF_ALO + row * BST + p * 4) = lo;
    }
    if (tid < 80) { sGp[2 * tid] = 1.f; sGp[2 * tid + 1] = 0.f; }
    __syncthreads();
    // Vw[n][f] = w_mem[n] . V_w[f] (one-time)
    for (int i = tid; i < N_ * E_; i += NTH) {
        int n_ = i / E_, f_ = i % E_;
        float acc = 0.f;
        for (int e_ = 0; e_ < E_; e_++) acc += sWm[n_ * SST + e_] * V_w[f_ * E_ + e_];
        sVw[n_ * SST + f_] = acc;
    }
    // s_0 = infos(t=0) computed in place
    for (int i = tid; i < NB * E_; i += NTH) {
        int bi = i / E_, e_ = i % E_;
        const float* ip = in_data + (long)(b0g + bi) * T_ * E_ + e_;
        float acc = 0.f;
#pragma unroll
        for (int l = 0; l < L_; l++) acc += sF[l * E_ + e_] * ip[(long)l * E_];
        sS[bi * SST + e_] = acc;
    }
    __syncthreads();

    const int stripe = w >> 1, nh = w & 1;
    const int m0 = stripe * 16;
    const int qr = lane >> 2, qc = lane & 3;
    const int r0 = m0 + qr, r1 = r0 + 8;
    const int grp = lane >> 3, lr = lane & 7;

    // helper prefetch slot indices (w >= 10; 192 threads over 400 elems)
    const int pf0 = tid - 320;             // 0..191
    const int pf1 = pf0 + 192;             // 192..383
    const int pf2 = pf0 + 384;             // 384..399 when pf0 < 16
    const bool pfh2 = (pf0 >= 0) && (pf2 < NB * E_);

    for (int t = 0; t < NCH; t++) {
        const float* sScur = sS + (t & 1) * NB * SST;

        float acc[7][4];
        float inv0 = 0.f, inv1 = 0.f;
        float v0[10], v1[10], v2[10];

        // ================= phase A: MMA | helpers (LDG issue -> sSW/gate) ==
        if (w < 10) {
            inv0 = rsqrtf(sGp[2 * r0] + sGp[2 * r0 + 1]);
            inv1 = rsqrtf(sGp[2 * r1] + sGp[2 * r1 + 1]);
#pragma unroll
            for (int j = 0; j < 7; j++)
#pragma unroll
                for (int q = 0; q < 4; q++) acc[j][q] = 0.f;
            const uint32_t aBase = smb + OFF_AHI;
            const uint32_t bhBase = smb + OFF_BHI;
#pragma unroll
            for (int k = 0; k < 7; k++) {
                // A fragments via ldmatrix (hi + lo)
                uint32_t ah[4], al[4];
                uint32_t aaddr = aBase + (uint32_t)((m0 + lr + ((grp & 1) << 3)) * BST
                               + k * 32 + ((grp >> 1) << 4));
                ldsm4(ah, aaddr);
                ldsm4(al, aaddr + 19200u);
                // B fragments: 3x ldsm4 pairs (+ tail only for nh==0)
                uint32_t bh[14], bl[14];
#pragma unroll
                for (int pq = 0; pq < 3; pq++) {
                    int t0 = nh * 7 + pq * 2;
                    uint32_t addr = bhBase + (uint32_t)((t0 * 8 + lr + (grp >> 1) * 8) * BST
                                  + k * 32 + (grp & 1) * 16);
                    ldsm4(&bh[pq * 4], addr);
                    ldsm4(&bl[pq * 4], addr + 26880u);
                }
#pragma unroll
                for (int j = 0; j < 6; j++) {
                    mma16816(acc[j], ah, &bh[2 * j]);
                    mma16816(acc[j], al, &bh[2 * j]);
                    mma16816(acc[j], ah, &bl[2 * j]);
                }
                if (nh == 0) {   // tail tile (j=6, cols 48-55); nh=1 tile 13 is pure pad
                    uint32_t addr = bhBase + (uint32_t)((6 * 8 + lr) * BST
                                  + k * 32 + ((lane >> 3) & 1) * 16);
                    uint32_t bht[2], blt[2];
                    ldsm2(bht, addr);
                    ldsm2(blt, addr + 26880u);
                    mma16816(acc[6], ah, bht);
                    mma16816(acc[6], al, bht);
                    mma16816(acc[6], ah, blt);
                }
            }
        } else {
            // ---- early-issue LDGs for s_{t+1} (hidden under whole phase A)
            if (t + 1 < NCH) {
                int bi0 = pf0 / E_, e0 = pf0 % E_;
                int bi1 = pf1 / E_, e1 = pf1 % E_;
                const float* ip0 = in_data + ((long)(b0g + bi0) * T_ + (t + 1) * L_) * E_ + e0;
                const float* ip1 = in_data + ((long)(b0g + bi1) * T_ + (t + 1) * L_) * E_ + e1;
#pragma unroll
                for (int l = 0; l < L_; l++) v0[l] = ip0[(long)l * E_];
#pragma unroll
                for (int l = 0; l < L_; l++) v1[l] = ip1[(long)l * E_];
                if (pfh2) {
                    int bi2 = pf2 / E_, e2 = pf2 % E_;
                    const float* ip2 = in_data + ((long)(b0g + bi2) * T_ + (t + 1) * L_) * E_ + e2;
#pragma unroll
                    for (int l = 0; l < L_; l++) v2[l] = ip2[(long)l * E_];
                }
            }
            int i = pf0;
            if (i < 100) {
                // sSW[bi][f=i] = s[bi] . W[f]
                int f_ = i;
                float a0 = 0.f, a1 = 0.f, a2 = 0.f, a3 = 0.f;
                const float* wp = sW + f_ * E_;
                for (int e4 = 0; e4 < 25; e4++) {
                    float4 wv = *(const float4*)(wp + e4 * 4);
                    float4 s0 = *(const float4*)(sScur + 0 * SST + e4 * 4);
                    float4 s1 = *(const float4*)(sScur + 1 * SST + e4 * 4);
                    float4 s2 = *(const float4*)(sScur + 2 * SST + e4 * 4);
                    float4 s3 = *(const float4*)(sScur + 3 * SST + e4 * 4);
                    a0 += wv.x * s0.x + wv.y * s0.y + wv.z * s0.z + wv.w * s0.w;
                    a1 += wv.x * s1.x + wv.y * s1.y + wv.z * s1.z + wv.w * s1.w;
                    a2 += wv.x * s2.x + wv.y * s2.y + wv.z * s2.z + wv.w * s2.w;
                    a3 += wv.x * s3.x + wv.y * s3.y + wv.z * s3.z + wv.w * s3.w;
                }
                sSW[0 * SST + f_] = a0;
                sSW[1 * SST + f_] = a1;
                sSW[2 * SST + f_] = a2;
                sSW[3 * SST + f_] = a3;
            } else if (i < 180) {
                // gate
                int row = i - 100;
                int bi = row / N_, ne = row % N_;
                const float* hp = sH + row * HST;
                const float* wp = sWm + ne * SST;
                const float* sp = sScur + bi * SST;
                float hs = 0.f, ws = 0.f;
                for (int e4 = 0; e4 < 25; e4++) {
                    float4 hv = *(const float4*)(hp + e4 * 4);
                    float4 wv = *(const float4*)(wp + e4 * 4);
                    float4 sv = *(const float4*)(sp + e4 * 4);
                    hs += hv.x * sv.x + hv.y * sv.y + hv.z * sv.z + hv.w * sv.w;
                    ws += wv.x * sv.x + wv.y * sv.y + wv.z * sv.z + wv.w * sv.w;
                }
                float inv = rsqrtf(sGp[2 * row] + sGp[2 * row + 1]);
                sG[row] = 1.f / (1.f + expf(-(inv * hs + ws)));
            }
        }
        __syncthreads();

        // ================= phase B: epilogue | prefetch combine+store ======
        if (w < 10) {
            float g0 = sG[r0], g1 = sG[r1];
            int bi0 = r0 / N_, ne0 = r0 % N_;
            int bi1 = r1 / N_, ne1 = r1 % N_;
            float ssq0 = 0.f, ssq1 = 0.f;
#pragma unroll
            for (int j = 0; j < 7; j++) {
                int f0 = (nh * 7 + j) * 8 + 2 * qc;
                if (f0 < 100) {
                    float2 vw0 = *(const float2*)(sVw + ne0 * SST + f0);
                    float2 sw0 = *(const float2*)(sSW + bi0 * SST + f0);
                    float2 hv0 = *(const float2*)(sH + r0 * HST + f0);
                    float c0 = acc[j][0] * inv0 + vw0.x + sw0.x;
                    float c1 = acc[j][1] * inv0 + vw0.y + sw0.y;
                    c0 = (c0 >= 0.f) ? c0 : adm * c0;
                    c1 = (c1 >= 0.f) ? c1 : adm * c1;
                    float n0v = hv0.x * inv0 + g0 * c0;
                    float n1v = hv0.y * inv0 + g0 * c1;
                    *(float2*)(sH + r0 * HST + f0) = make_float2(n0v, n1v);
                    ssq0 += n0v * n0v + n1v * n1v;
                    uint32_t hi0, lo0;
                    split2(n0v, n1v, hi0, lo0);
                    *(uint32_t*)(smc + OFF_AHI + r0 * BST + f0 * 2) = hi0;
                    *(uint32_t*)(smc + OFF_ALO + r0 * BST + f0 * 2) = lo0;

                    float2 vw1 = *(const float2*)(sVw + ne1 * SST + f0);
                    float2 sw1 = *(const float2*)(sSW + bi1 * SST + f0);
                    float2 hv1 = *(const float2*)(sH + r1 * HST + f0);
                    float d0 = acc[j][2] * inv1 + vw1.x + sw1.x;
                    float d1 = acc[j][3] * inv1 + vw1.y + sw1.y;
                    d0 = (d0 >= 0.f) ? d0 : adm * d0;
                    d1 = (d1 >= 0.f) ? d1 : adm * d1;
                    float m0v = hv1.x * inv1 + g1 * d0;
                    float m1v = hv1.y * inv1 + g1 * d1;
                    *(float2*)(sH + r1 * HST + f0) = make_float2(m0v, m1v);
                    ssq1 += m0v * m0v + m1v * m1v;
                    uint32_t hi1, lo1;
                    split2(m0v, m1v, hi1, lo1);
                    *(uint32_t*)(smc + OFF_AHI + r1 * BST + f0 * 2) = hi1;
                    *(uint32_t*)(smc + OFF_ALO + r1 * BST + f0 * 2) = lo1;
                }
            }
            ssq0 += __shfl_xor_sync(0xffffffffu, ssq0, 1);
            ssq0 += __shfl_xor_sync(0xffffffffu, ssq0, 2);
            ssq1 += __shfl_xor_sync(0xffffffffu, ssq1, 1);
            ssq1 += __shfl_xor_sync(0xffffffffu, ssq1, 2);
            if (qc == 0) {
                sGp[2 * r0 + nh] = ssq0;
                sGp[2 * r1 + nh] = ssq1;
            }
        } else if (t + 1 < NCH) {
            float* sNxt = sS + ((t + 1) & 1) * NB * SST;
            int bi0 = pf0 / E_, e0 = pf0 % E_;
            int bi1 = pf1 / E_, e1 = pf1 % E_;
            float a = 0.f, b = 0.f;
#pragma unroll
            for (int l = 0; l < L_; l++) a += sF[l * E_ + e0] * v0[l];
#pragma unroll
            for (int l = 0; l < L_; l++) b += sF[l * E_ + e1] * v1[l];
            sNxt[bi0 * SST + e0] = a;
            sNxt[bi1 * SST + e1] = b;
            if (pfh2) {
                int bi2 = pf2 / E_, e2 = pf2 % E_;
                float c = 0.f;
#pragma unroll
                for (int l = 0; l < L_; l++) c += sF[l * E_ + e2] * v2[l];
                sNxt[bi2 * SST + e2] = c;
            }
        }
        __syncthreads();
    }

    // ================= fused attention + head ==========================
    // 1) inv factors
    if (tid < 80) sG[tid] = rsqrtf(sGp[2 * tid] + sGp[2 * tid + 1]);
    __syncthreads();
    // 2) normalize sH in place; stage q into sS[0]; stage H_w into sW
    for (int i = tid; i < 80 * E_; i += NTH) {
        int row = i / E_, e_ = i % E_;
        sH[row * HST + e_] *= sG[row];
    }
    {
        float* sQ = sS;
        for (int i = tid; i < NB * E_; i += NTH) {
            int bi = i / E_, e_ = i % E_;
            const float* ip = in_data + ((long)(b0g + bi) * T_ + NCH * L_) * E_ + e_;
            float acc = 0.f;
#pragma unroll
            for (int l = 0; l < REST; l++) acc += sF[l * E_ + e_] * ip[(long)l * E_];
            sQ[bi * SST + e_] = acc;
        }
    }
    for (int i = tid; i < E_ * E_; i += NTH) sW[i] = H_w[i];
    __syncthreads();
    // 3) logits
    if (tid < 80) {
        int bi = tid / N_;
        const float* hp = sH + tid * HST;
        const float* qp = sS + bi * SST;
        float d = 0.f;
        for (int e4 = 0; e4 < 25; e4++) {
            float4 hv = *(const float4*)(hp + e4 * 4);
            float4 qv = *(const float4*)(qp + e4 * 4);
            d += hv.x * qv.x + hv.y * qv.y + hv.z * qv.z + hv.w * qv.w;
        }
        sGp[tid] = d;
    }
    __syncthreads();
    // 4) softmax per batch
    if (tid < NB) {
        const float* lp = sGp + tid * N_;
        float m = lp[0];
        for (int n = 1; n < N_; n++) m = fmaxf(m, lp[n]);
        float s = 0.f;
        float* pp = sG + tid * N_;
        for (int n = 0; n < N_; n++) { float ev = expf(lp[n] - m); pp[n] = ev; s += ev; }
        float inv = 1.f / s;
        for (int n = 0; n < N_; n++) pp[n] *= inv;
    }
    __syncthreads();
    // 5) u[bi][e] = sum_n p[n] h[bi*20+n][e]
    {
        float* sU = sS + NB * SST;
        for (int i = tid; i < NB * E_; i += NTH) {
            int bi = i / E_, e_ = i % E_;
            float u = 0.f;
#pragma unroll
            for (int n = 0; n < N_; n++) u += sG[bi * N_ + n] * sH[(bi * N_ + n) * HST + e_];
            sU[bi * SST + e_] = u;
        }
    }
    __syncthreads();
    // 6) y = q + u @ H_w^T + H_b ; prelu -> g_ya
    {
        const float* sQ = sS;
        const float* sU = sS + NB * SST;
        float ao = *a_out_p;
        for (int i = tid; i < NB * E_; i += NTH) {
            int bi = i / E_, f_ = i % E_;
            float acc = sQ[bi * SST + f_] + H_b[f_];
            const float* hw = sW + f_ * E_;
            const float* up = sU + bi * SST;
            for (int e4 = 0; e4 < 25; e4++) {
                float4 hv = *(const float4*)(hw + e4 * 4);
                float4 uv = *(const float4*)(up + e4 * 4);
                acc += hv.x * uv.x + hv.y * uv.y + hv.z * uv.z + hv.w * uv.w;
            }
            g_ya[(long)(b0g + bi) * E_ + f_] = (acc >= 0.f) ? acc : ao * acc;
        }
    }
}

// ============================================================
// K4: out[b][v] = ya[b] . R_w[v] + R_b[v]  (512 x 32000, K=100)
//     128x64 tiles, FFMA2.
// ============================================================
#define NP 50
#define K4_SMEM_FLOATS (128*NP*2 + 64*NP*2)
__global__ __launch_bounds__(256) void out_kernel(const float* __restrict__ R_w,
                                                  const float* __restrict__ R_b,
                                                  float* __restrict__ out) {
    extern __shared__ float osm[];
    float* sA2 = osm;                 // [p][bi] pairs, 128 rows
    float* sB2 = osm + 128 * NP * 2;  // [p][vi] pairs, 64 cols
    int tid = threadIdx.x;
    int v0 = blockIdx.x * 64, b0 = blockIdx.y * 128;
    for (int i = tid; i < 128 * NP; i += 256) {
        int bi = i / NP, p = i % NP;
        float2 v = *(const float2*)(g_ya + (long)(b0 + bi) * E_ + 2 * p);
        sA2[(p * 128 + bi) * 2]     = v.x;
        sA2[(p * 128 + bi) * 2 + 1] = v.y;
    }
    for (int i = tid; i < 64 * NP; i += 256) {
        int vi = i / NP, p = i % NP;
        float2 v = *(const float2*)(R_w + (long)(v0 + vi) * E_ + 2 * p);
        sB2[(p * 64 + vi) * 2]     = v.x;
        sB2[(p * 64 + vi) * 2 + 1] = v.y;
    }
    __syncthreads();
    int bi8 = (tid >> 4) << 3;    // rows bi8..bi8+7
    int vj  = tid & 15;           // cols {vj, vj+16, vj+32, vj+48}
    unsigned long long acc2[8][4];
#pragma unroll
    for (int k = 0; k < 8; k++)
#pragma unroll
        for (int j = 0; j < 4; j++) acc2[k][j] = 0ull;
#pragma unroll 2
    for (int p = 0; p < NP; p++) {
        unsigned long long a2[8], b2[4];
#pragma unroll
        for (int j = 0; j < 4; j++) b2[j] = lds2(sB2 + (p * 64 + vj + 16 * j) * 2);
#pragma unroll
        for (int k = 0; k < 8; k++) a2[k] = lds2(sA2 + (p * 128 + bi8 + k) * 2);
#pragma unroll
        for (int k = 0; k < 8; k++)
#pragma unroll
            for (int j = 0; j < 4; j++) ffma2(acc2[k][j], a2[k], b2[j]);
    }
    float rb[4];
#pragma unroll
    for (int j = 0; j < 4; j++) rb[j] = R_b[v0 + vj + 16 * j];
#pragma unroll
    for (int k = 0; k < 8; k++) {
#pragma unroll
        for (int j = 0; j < 4; j++) {
            out[(long)(b0 + bi8 + k) * V_ + v0 + vj + 16 * j] = hadd2(acc2[k][j]) + rb[j];
        }
    }
}

// ============================================================
extern "C" void kernel_launch(void* const* d_in, const int* in_sizes, int n_in,
                              void* d_out, int out_size) {
    const float* in_data = (const float*)d_in[0];
    const float* f       = (const float*)d_in[1];
    const float* h0      = (const float*)d_in[2];
    const float* w_mem   = (const float*)d_in[3];
    const float* U_w     = (const float*)d_in[4];
    const float* V_w     = (const float*)d_in[5];
    const float* W_w     = (const float*)d_in[6];
    const float* a_dm    = (const float*)d_in[7];
    const float* H_w     = (const float*)d_in[8];
    const float* H_b     = (const float*)d_in[9];
    const float* R_w     = (const float*)d_in[10];
    const float* R_b     = (const float*)d_in[11];
    const float* a_out   = (const float*)d_in[12];
    float* out = (float*)d_out;

    cudaFuncSetAttribute(scan_mma_kernel, cudaFuncAttributeMaxDynamicSharedMemorySize,
                         SCAN_SMEM);
    const int k4_smem = K4_SMEM_FLOATS * (int)sizeof(float);
    cudaFuncSetAttribute(out_kernel, cudaFuncAttributeMaxDynamicSharedMemorySize,
                         k4_smem);

    scan_mma_kernel<<<B_ / NB, NTH, SCAN_SMEM>>>(U_w, V_w, W_w, w_mem, h0, a_dm,
                                                 in_data, f, H_w, H_b, a_out);
    dim3 g4(V_ / 64, B_ / 128);
    out_kernel<<<g4, 256, k4_smem>>>(R_w, R_b, out);
}

// round 11
// speedup vs baseline: 1.3070x; 1.1159x over previous
#include <cuda_runtime.h>
#include <cuda_bf16.h>
#include <math.h>
#include <stdint.h>

#define B_   512
#define T_   1005
#define E_   100
#define L_   10
#define N_   20
#define V_   32000
#define NCH  100      // n_full = T/L
#define REST 5        // T % L

// ---- scratch (no allocations allowed) ----
__device__ float g_ya[B_ * E_];                 // prelu(y)
__device__ uint32_t g_Rhi[V_ * 60];             // R_w bf16-hi pairs, 240B rows
__device__ uint32_t g_Rlo[V_ * 60];
__device__ uint32_t g_Yhi[B_ * 60];             // ya bf16-hi pairs
__device__ uint32_t g_Ylo[B_ * 60];

// ---- warp MMA helpers (portable PTX, sm_80+) ----
__device__ __forceinline__ uint32_t smem_u32(const void* p) {
    uint32_t a;
    asm("{ .reg .u64 t; cvta.to.shared.u64 t, %1; cvt.u32.u64 %0, t; }"
        : "=r"(a) : "l"(p));
    return a;
}
__device__ __forceinline__ void ldsm4(uint32_t* r, uint32_t a) {
    asm volatile("ldmatrix.sync.aligned.m8n8.x4.shared.b16 {%0,%1,%2,%3}, [%4];"
        : "=r"(r[0]), "=r"(r[1]), "=r"(r[2]), "=r"(r[3]) : "r"(a));
}
__device__ __forceinline__ void ldsm2(uint32_t* r, uint32_t a) {
    asm volatile("ldmatrix.sync.aligned.m8n8.x2.shared.b16 {%0,%1}, [%2];"
        : "=r"(r[0]), "=r"(r[1]) : "r"(a));
}
__device__ __forceinline__ void mma16816(float* c, const uint32_t* a, const uint32_t* b) {
    asm volatile(
        "mma.sync.aligned.m16n8k16.row.col.f32.bf16.bf16.f32 "
        "{%0,%1,%2,%3}, {%4,%5,%6,%7}, {%8,%9}, {%0,%1,%2,%3};"
        : "+f"(c[0]), "+f"(c[1]), "+f"(c[2]), "+f"(c[3])
        : "r"(a[0]), "r"(a[1]), "r"(a[2]), "r"(a[3]), "r"(b[0]), "r"(b[1]));
}
// split two fp32 into packed bf16 hi + residual lo
__device__ __forceinline__ void split2(float x0, float x1, uint32_t& hi, uint32_t& lo) {
    __nv_bfloat162 bh = __floats2bfloat162_rn(x0, x1);
    uint32_t h = *reinterpret_cast<uint32_t*>(&bh);
    float hf0 = __uint_as_float(h << 16);
    float hf1 = __uint_as_float(h & 0xffff0000u);
    __nv_bfloat162 bl = __floats2bfloat162_rn(x0 - hf0, x1 - hf1);
    hi = h;
    lo = *reinterpret_cast<uint32_t*>(&bl);
}

// ============================================================
// K2: persistent scan on warp MMA (bf16x3). 128 CTAs x 4 batches.
//     (R10 config, frozen)
// ============================================================
#define NB   4
#define NTH  512
#define BST  240
#define HST  108
#define SST  104

#define OFF_AHI 0
#define OFF_ALO 19200
#define OFF_BHI 38400
#define OFF_BLO 65280
#define OFF_H   92160
#define OFF_W   126720
#define OFF_WM  166720
#define OFF_VW  175040
#define OFF_S   183360
#define OFF_SSW 186688
#define OFF_G   188352
#define OFF_GP  188672
#define OFF_F   189312
#define SCAN_SMEM 193312

__global__ __launch_bounds__(NTH, 1) void scan_mma_kernel(
    const float* __restrict__ U_w, const float* __restrict__ V_w,
    const float* __restrict__ W_w, const float* __restrict__ w_mem,
    const float* __restrict__ h0,  const float* __restrict__ a_dm_p,
    const float* __restrict__ in_data, const float* __restrict__ f_w,
    const float* __restrict__ H_w, const float* __restrict__ H_b,
    const float* __restrict__ a_out_p)
{
    extern __shared__ char smc[];
    float* sH  = (float*)(smc + OFF_H);
    float* sW  = (float*)(smc + OFF_W);
    float* sWm = (float*)(smc + OFF_WM);
    float* sVw = (float*)(smc + OFF_VW);
    float* sS  = (float*)(smc + OFF_S);
    float* sSW = (float*)(smc + OFF_SSW);
    float* sG  = (float*)(smc + OFF_G);
    float* sGp = (float*)(smc + OFF_GP);
    float* sF  = (float*)(smc + OFF_F);

    const int tid = threadIdx.x;
    const int w = tid >> 5;
    const int lane = tid & 31;
    const int b0g = blockIdx.x * NB;
    const float adm = *a_dm_p;
    const uint32_t smb = smem_u32(smc);

    for (int i = tid; i < OFF_H / 4; i += NTH) ((uint32_t*)smc)[i] = 0;
    __syncthreads();

    for (int i = tid; i < E_ * 50; i += NTH) {
        int f_ = i / 50, p = i % 50;
        float2 uv = *(const float2*)(U_w + f_ * E_ + 2 * p);
        uint32_t hi, lo;
        split2(uv.x, uv.y, hi, lo);
        *(uint32_t*)(smc + OFF_BHI + f_ * BST + p * 4) = hi;
        *(uint32_t*)(smc + OFF_BLO + f_ * BST + p * 4) = lo;
    }
    for (int i = tid; i < E_ * E_; i += NTH) sW[i] = W_w[i];
    for (int i = tid; i < L_ * E_; i += NTH) sF[i] = f_w[i];
    for (int i = tid; i < N_ * E_; i += NTH) {
        int n_ = i / E_, e_ = i % E_;
        sWm[n_ * SST + e_] = w_mem[i];
    }
    for (int i = tid; i < 80 * 50; i += NTH) {
        int row = i / 50, p = i % 50;
        float2 hv = *(const float2*)(h0 + (row % N_) * E_ + 2 * p);
        *(float2*)(sH + row * HST + 2 * p) = hv;
        uint32_t hi, lo;
        split2(hv.x, hv.y, hi, lo);
        *(uint32_t*)(smc + OFF_AHI + row * BST + p * 4) = hi;
        *(uint32_t*)(smc + OFF_ALO + row * BST + p * 4) = lo;
    }
    if (tid < 80) { sGp[2 * tid] = 1.f; sGp[2 * tid + 1] = 0.f; }
    __syncthreads();
    for (int i = tid; i < N_ * E_; i += NTH) {
        int n_ = i / E_, f_ = i % E_;
        float acc = 0.f;
        for (int e_ = 0; e_ < E_; e_++) acc += sWm[n_ * SST + e_] * V_w[f_ * E_ + e_];
        sVw[n_ * SST + f_] = acc;
    }
    for (int i = tid; i < NB * E_; i += NTH) {
        int bi = i / E_, e_ = i % E_;
        const float* ip = in_data + (long)(b0g + bi) * T_ * E_ + e_;
        float acc = 0.f;
#pragma unroll
        for (int l = 0; l < L_; l++) acc += sF[l * E_ + e_] * ip[(long)l * E_];
        sS[bi * SST + e_] = acc;
    }
    __syncthreads();

    const int stripe = w >> 1, nh = w & 1;
    const int m0 = stripe * 16;
    const int qr = lane >> 2, qc = lane & 3;
    const int r0 = m0 + qr, r1 = r0 + 8;
    const int grp = lane >> 3, lr = lane & 7;

    const int pf0 = tid - 320;
    const int pf1 = pf0 + 192;
    const int pf2 = pf0 + 384;
    const bool pfh2 = (pf0 >= 0) && (pf2 < NB * E_);

    for (int t = 0; t < NCH; t++) {
        const float* sScur = sS + (t & 1) * NB * SST;

        float acc[7][4];
        float inv0 = 0.f, inv1 = 0.f;
        float v0[10], v1[10], v2[10];

        if (w < 10) {
            inv0 = rsqrtf(sGp[2 * r0] + sGp[2 * r0 + 1]);
            inv1 = rsqrtf(sGp[2 * r1] + sGp[2 * r1 + 1]);
#pragma unroll
            for (int j = 0; j < 7; j++)
#pragma unroll
                for (int q = 0; q < 4; q++) acc[j][q] = 0.f;
            const uint32_t aBase = smb + OFF_AHI;
            const uint32_t bhBase = smb + OFF_BHI;
#pragma unroll
            for (int k = 0; k < 7; k++) {
                uint32_t ah[4], al[4];
                uint32_t aaddr = aBase + (uint32_t)((m0 + lr + ((grp & 1) << 3)) * BST
                               + k * 32 + ((grp >> 1) << 4));
                ldsm4(ah, aaddr);
                ldsm4(al, aaddr + 19200u);
                uint32_t bh[14], bl[14];
#pragma unroll
                for (int pq = 0; pq < 3; pq++) {
                    int t0 = nh * 7 + pq * 2;
                    uint32_t addr = bhBase + (uint32_t)((t0 * 8 + lr + (grp >> 1) * 8) * BST
                                  + k * 32 + (grp & 1) * 16);
                    ldsm4(&bh[pq * 4], addr);
                    ldsm4(&bl[pq * 4], addr + 26880u);
                }
#pragma unroll
                for (int j = 0; j < 6; j++) {
                    mma16816(acc[j], ah, &bh[2 * j]);
                    mma16816(acc[j], al, &bh[2 * j]);
                    mma16816(acc[j], ah, &bl[2 * j]);
                }
                if (nh == 0) {
                    uint32_t addr = bhBase + (uint32_t)((6 * 8 + lr) * BST
                                  + k * 32 + ((lane >> 3) & 1) * 16);
                    uint32_t bht[2], blt[2];
                    ldsm2(bht, addr);
                    ldsm2(blt, addr + 26880u);
                    mma16816(acc[6], ah, bht);
                    mma16816(acc[6], al, bht);
                    mma16816(acc[6], ah, blt);
                }
            }
        } else {
            if (t + 1 < NCH) {
                int bi0 = pf0 / E_, e0 = pf0 % E_;
                int bi1 = pf1 / E_, e1 = pf1 % E_;
                const float* ip0 = in_data + ((long)(b0g + bi0) * T_ + (t + 1) * L_) * E_ + e0;
                const float* ip1 = in_data + ((long)(b0g + bi1) * T_ + (t + 1) * L_) * E_ + e1;
#pragma unroll
                for (int l = 0; l < L_; l++) v0[l] = ip0[(long)l * E_];
#pragma unroll
                for (int l = 0; l < L_; l++) v1[l] = ip1[(long)l * E_];
                if (pfh2) {
                    int bi2 = pf2 / E_, e2 = pf2 % E_;
                    const float* ip2 = in_data + ((long)(b0g + bi2) * T_ + (t + 1) * L_) * E_ + e2;
#pragma unroll
                    for (int l = 0; l < L_; l++) v2[l] = ip2[(long)l * E_];
                }
            }
            int i = pf0;
            if (i < 100) {
                int f_ = i;
                float a0 = 0.f, a1 = 0.f, a2 = 0.f, a3 = 0.f;
                const float* wp = sW + f_ * E_;
                for (int e4 = 0; e4 < 25; e4++) {
                    float4 wv = *(const float4*)(wp + e4 * 4);
                    float4 s0 = *(const float4*)(sScur + 0 * SST + e4 * 4);
                    float4 s1 = *(const float4*)(sScur + 1 * SST + e4 * 4);
                    float4 s2 = *(const float4*)(sScur + 2 * SST + e4 * 4);
                    float4 s3 = *(const float4*)(sScur + 3 * SST + e4 * 4);
                    a0 += wv.x * s0.x + wv.y * s0.y + wv.z * s0.z + wv.w * s0.w;
                    a1 += wv.x * s1.x + wv.y * s1.y + wv.z * s1.z + wv.w * s1.w;
                    a2 += wv.x * s2.x + wv.y * s2.y + wv.z * s2.z + wv.w * s2.w;
                    a3 += wv.x * s3.x + wv.y * s3.y + wv.z * s3.z + wv.w * s3.w;
                }
                sSW[0 * SST + f_] = a0;
                sSW[1 * SST + f_] = a1;
                sSW[2 * SST + f_] = a2;
                sSW[3 * SST + f_] = a3;
            } else if (i < 180) {
                int row = i - 100;
                int bi = row / N_, ne = row % N_;
                const float* hp = sH + row * HST;
                const float* wp = sWm + ne * SST;
                const float* sp = sScur + bi * SST;
                float hs = 0.f, ws = 0.f;
                for (int e4 = 0; e4 < 25; e4++) {
                    float4 hv = *(const float4*)(hp + e4 * 4);
                    float4 wv = *(const float4*)(wp + e4 * 4);
                    float4 sv = *(const float4*)(sp + e4 * 4);
                    hs += hv.x * sv.x + hv.y * sv.y + hv.z * sv.z + hv.w * sv.w;
                    ws += wv.x * sv.x + wv.y * sv.y + wv.z * sv.z + wv.w * sv.w;
                }
                float inv = rsqrtf(sGp[2 * row] + sGp[2 * row + 1]);
                sG[row] = 1.f / (1.f + expf(-(inv * hs + ws)));
            }
        }
        __syncthreads();

        if (w < 10) {
            float g0 = sG[r0], g1 = sG[r1];
            int bi0 = r0 / N_, ne0 = r0 % N_;
            int bi1 = r1 / N_, ne1 = r1 % N_;
            float ssq0 = 0.f, ssq1 = 0.f;
#pragma unroll
            for (int j = 0; j < 7; j++) {
                int f0 = (nh * 7 + j) * 8 + 2 * qc;
                if (f0 < 100) {
                    float2 vw0 = *(const float2*)(sVw + ne0 * SST + f0);
                    float2 sw0 = *(const float2*)(sSW + bi0 * SST + f0);
                    float2 hv0 = *(const float2*)(sH + r0 * HST + f0);
                    float c0 = acc[j][0] * inv0 + vw0.x + sw0.x;
                    float c1 = acc[j][1] * inv0 + vw0.y + sw0.y;
                    c0 = (c0 >= 0.f) ? c0 : adm * c0;
                    c1 = (c1 >= 0.f) ? c1 : adm * c1;
                    float n0v = hv0.x * inv0 + g0 * c0;
                    float n1v = hv0.y * inv0 + g0 * c1;
                    *(float2*)(sH + r0 * HST + f0) = make_float2(n0v, n1v);
                    ssq0 += n0v * n0v + n1v * n1v;
                    uint32_t hi0, lo0;
                    split2(n0v, n1v, hi0, lo0);
                    *(uint32_t*)(smc + OFF_AHI + r0 * BST + f0 * 2) = hi0;
                    *(uint32_t*)(smc + OFF_ALO + r0 * BST + f0 * 2) = lo0;

                    float2 vw1 = *(const float2*)(sVw + ne1 * SST + f0);
                    float2 sw1 = *(const float2*)(sSW + bi1 * SST + f0);
                    float2 hv1 = *(const float2*)(sH + r1 * HST + f0);
                    float d0 = acc[j][2] * inv1 + vw1.x + sw1.x;
                    float d1 = acc[j][3] * inv1 + vw1.y + sw1.y;
                    d0 = (d0 >= 0.f) ? d0 : adm * d0;
                    d1 = (d1 >= 0.f) ? d1 : adm * d1;
                    float m0v = hv1.x * inv1 + g1 * d0;
                    float m1v = hv1.y * inv1 + g1 * d1;
                    *(float2*)(sH + r1 * HST + f0) = make_float2(m0v, m1v);
                    ssq1 += m0v * m0v + m1v * m1v;
                    uint32_t hi1, lo1;
                    split2(m0v, m1v, hi1, lo1);
                    *(uint32_t*)(smc + OFF_AHI + r1 * BST + f0 * 2) = hi1;
                    *(uint32_t*)(smc + OFF_ALO + r1 * BST + f0 * 2) = lo1;
                }
            }
            ssq0 += __shfl_xor_sync(0xffffffffu, ssq0, 1);
            ssq0 += __shfl_xor_sync(0xffffffffu, ssq0, 2);
            ssq1 += __shfl_xor_sync(0xffffffffu, ssq1, 1);
            ssq1 += __shfl_xor_sync(0xffffffffu, ssq1, 2);
            if (qc == 0) {
                sGp[2 * r0 + nh] = ssq0;
                sGp[2 * r1 + nh] = ssq1;
            }
        } else if (t + 1 < NCH) {
            float* sNxt = sS + ((t + 1) & 1) * NB * SST;
            int bi0 = pf0 / E_, e0 = pf0 % E_;
            int bi1 = pf1 / E_, e1 = pf1 % E_;
            float a = 0.f, b = 0.f;
#pragma unroll
            for (int l = 0; l < L_; l++) a += sF[l * E_ + e0] * v0[l];
#pragma unroll
            for (int l = 0; l < L_; l++) b += sF[l * E_ + e1] * v1[l];
            sNxt[bi0 * SST + e0] = a;
            sNxt[bi1 * SST + e1] = b;
            if (pfh2) {
                int bi2 = pf2 / E_, e2 = pf2 % E_;
                float c = 0.f;
#pragma unroll
                for (int l = 0; l < L_; l++) c += sF[l * E_ + e2] * v2[l];
                sNxt[bi2 * SST + e2] = c;
            }
        }
        __syncthreads();
    }

    // ================= fused attention + head ==========================
    if (tid < 80) sG[tid] = rsqrtf(sGp[2 * tid] + sGp[2 * tid + 1]);
    __syncthreads();
    for (int i = tid; i < 80 * E_; i += NTH) {
        int row = i / E_, e_ = i % E_;
        sH[row * HST + e_] *= sG[row];
    }
    {
        float* sQ = sS;
        for (int i = tid; i < NB * E_; i += NTH) {
            int bi = i / E_, e_ = i % E_;
            const float* ip = in_data + ((long)(b0g + bi) * T_ + NCH * L_) * E_ + e_;
            float acc = 0.f;
#pragma unroll
            for (int l = 0; l < REST; l++) acc += sF[l * E_ + e_] * ip[(long)l * E_];
            sQ[bi * SST + e_] = acc;
        }
    }
    for (int i = tid; i < E_ * E_; i += NTH) sW[i] = H_w[i];
    __syncthreads();
    if (tid < 80) {
        int bi = tid / N_;
        const float* hp = sH + tid * HST;
        const float* qp = sS + bi * SST;
        float d = 0.f;
        for (int e4 = 0; e4 < 25; e4++) {
            float4 hv = *(const float4*)(hp + e4 * 4);
            float4 qv = *(const float4*)(qp + e4 * 4);
            d += hv.x * qv.x + hv.y * qv.y + hv.z * qv.z + hv.w * qv.w;
        }
        sGp[tid] = d;
    }
    __syncthreads();
    if (tid < NB) {
        const float* lp = sGp + tid * N_;
        float m = lp[0];
        for (int n = 1; n < N_; n++) m = fmaxf(m, lp[n]);
        float s = 0.f;
        float* pp = sG + tid * N_;
        for (int n = 0; n < N_; n++) { float ev = expf(lp[n] - m); pp[n] = ev; s += ev; }
        float inv = 1.f / s;
        for (int n = 0; n < N_; n++) pp[n] *= inv;
    }
    __syncthreads();
    {
        float* sU = sS + NB * SST;
        for (int i = tid; i < NB * E_; i += NTH) {
            int bi = i / E_, e_ = i % E_;
            float u = 0.f;
#pragma unroll
            for (int n = 0; n < N_; n++) u += sG[bi * N_ + n] * sH[(bi * N_ + n) * HST + e_];
            sU[bi * SST + e_] = u;
        }
    }
    __syncthreads();
    {
        const float* sQ = sS;
        const float* sU = sS + NB * SST;
        float ao = *a_out_p;
        for (int i = tid; i < NB * E_; i += NTH) {
            int bi = i / E_, f_ = i % E_;
            float acc = sQ[bi * SST + f_] + H_b[f_];
            const float* hw = sW + f_ * E_;
            const float* up = sU + bi * SST;
            for (int e4 = 0; e4 < 25; e4++) {
                float4 hv = *(const float4*)(hw + e4 * 4);
                float4 uv = *(const float4*)(up + e4 * 4);
                acc += hv.x * uv.x + hv.y * uv.y + hv.z * uv.z + hv.w * uv.w;
            }
            g_ya[(long)(b0g + bi) * E_ + f_] = (acc >= 0.f) ? acc : ao * acc;
        }
    }
}

// ============================================================
// K3: convert R_w and g_ya into packed bf16 hi/lo pair rows
//     (60 u32 per row = 240 B; pairs >= 50 zeroed)
// ============================================================
__global__ void convert_kernel(const float* __restrict__ R_w) {
    int idx = blockIdx.x * 256 + threadIdx.x;
    const int RTOT = V_ * 60;
    if (idx < RTOT) {
        int v = idx / 60, p = idx % 60;
        uint32_t hi = 0, lo = 0;
        if (p < 50) {
            float2 rv = *(const float2*)(R_w + (long)v * E_ + 2 * p);
            split2(rv.x, rv.y, hi, lo);
        }
        g_Rhi[idx] = hi;
        g_Rlo[idx] = lo;
    } else if (idx < RTOT + B_ * 60) {
        int i = idx - RTOT;
        int b = i / 60, p = i % 60;
        uint32_t hi = 0, lo = 0;
        if (p < 50) {
            float2 yv = *(const float2*)(g_ya + (long)b * E_ + 2 * p);
            split2(yv.x, yv.y, hi, lo);
        }
        g_Yhi[i] = hi;
        g_Ylo[i] = lo;
    }
}

// ============================================================
// K4: out = ya @ R_w^T + R_b on HMMA (bf16x3). 128b x 128v tiles.
// ============================================================
#define O_AHI 0
#define O_ALO 30720
#define O_BHI 61440
#define O_BLO 92160
#define OUT_SMEM 122880

__global__ __launch_bounds__(256, 1) void out_mma_kernel(
    const float* __restrict__ R_b, float* __restrict__ out)
{
    extern __shared__ char smo[];
    const int tid = threadIdx.x;
    const int w = tid >> 5;
    const int lane = tid & 31;
    const int v0 = blockIdx.x * 128;
    const int b0 = blockIdx.y * 128;
    const uint32_t smb = smem_u32(smo);

    // stage A (ya) and B (R) tiles: 128 rows x 60 u32 each, hi+lo
    uint32_t* sAhi = (uint32_t*)(smo + O_AHI);
    uint32_t* sAlo = (uint32_t*)(smo + O_ALO);
    uint32_t* sBhi = (uint32_t*)(smo + O_BHI);
    uint32_t* sBlo = (uint32_t*)(smo + O_BLO);
    for (int i = tid; i < 128 * 60; i += 256) {
        int r = i / 60, p = i % 60;
        sAhi[i] = g_Yhi[(b0 + r) * 60 + p];
        sAlo[i] = g_Ylo[(b0 + r) * 60 + p];
        sBhi[i] = g_Rhi[(long)(v0 + r) * 60 + p];
        sBlo[i] = g_Rlo[(long)(v0 + r) * 60 + p];
    }
    __syncthreads();

    // warp tile: m32 (mw = w>>1) x n64 (nw = w&1)
    const int mw = w >> 1, nw = w & 1;
    const int m0 = mw * 32;
    const int n0 = nw * 64;
    const int qr = lane >> 2, qc = lane & 3;
    const int grp = lane >> 3, lr = lane & 7;

    float acc[2][8][4];
#pragma unroll
    for (int mh = 0; mh < 2; mh++)
#pragma unroll
        for (int j = 0; j < 8; j++)
#pragma unroll
            for (int q = 0; q < 4; q++) acc[mh][j][q] = 0.f;

#pragma unroll
    for (int k = 0; k < 7; k++) {
        uint32_t ah[2][4], al[2][4];
#pragma unroll
        for (int mh = 0; mh < 2; mh++) {
            uint32_t aaddr = smb + O_AHI + (uint32_t)((m0 + 16 * mh + lr + ((grp & 1) << 3)) * 240
                           + k * 32 + ((grp >> 1) << 4));
            ldsm4(ah[mh], aaddr);
            ldsm4(al[mh], aaddr + 30720u);
        }
#pragma unroll
        for (int pq = 0; pq < 4; pq++) {
            uint32_t addr = smb + O_BHI + (uint32_t)((n0 + pq * 16 + lr + (grp >> 1) * 8) * 240
                          + k * 32 + (grp & 1) * 16);
            uint32_t bh[4], bl[4];
            ldsm4(bh, addr);
            ldsm4(bl, addr + 30720u);
#pragma unroll
            for (int mh = 0; mh < 2; mh++)
#pragma unroll
                for (int jj = 0; jj < 2; jj++) {
                    int j = pq * 2 + jj;
                    mma16816(acc[mh][j], ah[mh], &bh[2 * jj]);
                    mma16816(acc[mh][j], al[mh], &bh[2 * jj]);
                    mma16816(acc[mh][j], ah[mh], &bl[2 * jj]);
                }
        }
    }

    // epilogue: out[b][v] = acc + R_b[v]
#pragma unroll
    for (int mh = 0; mh < 2; mh++) {
        int ra = b0 + m0 + 16 * mh + qr;
        int rb2 = ra + 8;
#pragma unroll
        for (int j = 0; j < 8; j++) {
            int c = v0 + n0 + j * 8 + 2 * qc;
            float2 rb = *(const float2*)(R_b + c);
            float2 o0 = make_float2(acc[mh][j][0] + rb.x, acc[mh][j][1] + rb.y);
            float2 o1 = make_float2(acc[mh][j][2] + rb.x, acc[mh][j][3] + rb.y);
            *(float2*)(out + (long)ra * V_ + c) = o0;
            *(float2*)(out + (long)rb2 * V_ + c) = o1;
        }
    }
}

// ============================================================
extern "C" void kernel_launch(void* const* d_in, const int* in_sizes, int n_in,
                              void* d_out, int out_size) {
    const float* in_data = (const float*)d_in[0];
    const float* f       = (const float*)d_in[1];
    const float* h0      = (const float*)d_in[2];
    const float* w_mem   = (const float*)d_in[3];
    const float* U_w     = (const float*)d_in[4];
    const float* V_w     = (const float*)d_in[5];
    const float* W_w     = (const float*)d_in[6];
    const float* a_dm    = (const float*)d_in[7];
    const float* H_w     = (const float*)d_in[8];
    const float* H_b     = (const float*)d_in[9];
    const float* R_w     = (const float*)d_in[10];
    const float* R_b     = (const float*)d_in[11];
    const float* a_out   = (const float*)d_in[12];
    float* out = (float*)d_out;

    cudaFuncSetAttribute(scan_mma_kernel, cudaFuncAttributeMaxDynamicSharedMemorySize,
                         SCAN_SMEM);
    cudaFuncSetAttribute(out_mma_kernel, cudaFuncAttributeMaxDynamicSharedMemorySize,
                         OUT_SMEM);

    scan_mma_kernel<<<B_ / NB, NTH, SCAN_SMEM>>>(U_w, V_w, W_w, w_mem, h0, a_dm,
                                                 in_data, f, H_w, H_b, a_out);
    const int conv_total = V_ * 60 + B_ * 60;
    convert_kernel<<<(conv_total + 255) / 256, 256>>>(R_w);
    dim3 g4(V_ / 128, B_ / 128);
    out_mma_kernel<<<g4, 256, OUT_SMEM>>>(R_b, out);
}

// round 12
// speedup vs baseline: 1.4334x; 1.0967x over previous
#include <cuda_runtime.h>
#include <cuda_bf16.h>
#include <cuda_fp16.h>
#include <math.h>
#include <stdint.h>

#define B_   512
#define T_   1005
#define E_   100
#define L_   10
#define N_   20
#define V_   32000
#define NCH  100      // n_full = T/L
#define REST 5        // T % L

// ---- scratch (no allocations allowed) ----
__device__ float g_ya[B_ * E_];                 // prelu(y)
__device__ uint32_t g_Rhi[V_ * 60];             // R_w bf16-hi pairs, 240B rows
__device__ uint32_t g_Rlo[V_ * 60];
__device__ uint32_t g_Yhi[B_ * 60];             // ya bf16-hi pairs
__device__ uint32_t g_Ylo[B_ * 60];

// ---- warp MMA helpers (portable PTX, sm_80+) ----
__device__ __forceinline__ uint32_t smem_u32(const void* p) {
    uint32_t a;
    asm("{ .reg .u64 t; cvta.to.shared.u64 t, %1; cvt.u32.u64 %0, t; }"
        : "=r"(a) : "l"(p));
    return a;
}
__device__ __forceinline__ void ldsm4(uint32_t* r, uint32_t a) {
    asm volatile("ldmatrix.sync.aligned.m8n8.x4.shared.b16 {%0,%1,%2,%3}, [%4];"
        : "=r"(r[0]), "=r"(r[1]), "=r"(r[2]), "=r"(r[3]) : "r"(a));
}
__device__ __forceinline__ void ldsm2(uint32_t* r, uint32_t a) {
    asm volatile("ldmatrix.sync.aligned.m8n8.x2.shared.b16 {%0,%1}, [%2];"
        : "=r"(r[0]), "=r"(r[1]) : "r"(a));
}
// bf16 MMA (out GEMM)
__device__ __forceinline__ void mma16816(float* c, const uint32_t* a, const uint32_t* b) {
    asm volatile(
        "mma.sync.aligned.m16n8k16.row.col.f32.bf16.bf16.f32 "
        "{%0,%1,%2,%3}, {%4,%5,%6,%7}, {%8,%9}, {%0,%1,%2,%3};"
        : "+f"(c[0]), "+f"(c[1]), "+f"(c[2]), "+f"(c[3])
        : "r"(a[0]), "r"(a[1]), "r"(a[2]), "r"(a[3]), "r"(b[0]), "r"(b[1]));
}
// fp16 MMA (scan GEMM)
__device__ __forceinline__ void mma16816h(float* c, const uint32_t* a, const uint32_t* b) {
    asm volatile(
        "mma.sync.aligned.m16n8k16.row.col.f32.f16.f16.f32 "
        "{%0,%1,%2,%3}, {%4,%5,%6,%7}, {%8,%9}, {%0,%1,%2,%3};"
        : "+f"(c[0]), "+f"(c[1]), "+f"(c[2]), "+f"(c[3])
        : "r"(a[0]), "r"(a[1]), "r"(a[2]), "r"(a[3]), "r"(b[0]), "r"(b[1]));
}
// split two fp32 into packed bf16 hi + residual lo (out GEMM convert)
__device__ __forceinline__ void split2(float x0, float x1, uint32_t& hi, uint32_t& lo) {
    __nv_bfloat162 bh = __floats2bfloat162_rn(x0, x1);
    uint32_t h = *reinterpret_cast<uint32_t*>(&bh);
    float hf0 = __uint_as_float(h << 16);
    float hf1 = __uint_as_float(h & 0xffff0000u);
    __nv_bfloat162 bl = __floats2bfloat162_rn(x0 - hf0, x1 - hf1);
    hi = h;
    lo = *reinterpret_cast<uint32_t*>(&bl);
}
// split two fp32 into packed fp16 hi + residual lo (scan)
__device__ __forceinline__ void split2h(float x0, float x1, uint32_t& hi, uint32_t& lo) {
    __half2 h2 = __floats2half2_rn(x0, x1);
    float f0 = __half2float(__low2half(h2));
    float f1 = __half2float(__high2half(h2));
    __half2 l2 = __floats2half2_rn(x0 - f0, x1 - f1);
    hi = *reinterpret_cast<uint32_t*>(&h2);
    lo = *reinterpret_cast<uint32_t*>(&l2);
}

// ============================================================
// K2: persistent scan on warp MMA (fp16 x2: (A_hi+A_lo)·B_hi).
//     128 CTAs x 4 batches; 10 MMA + 6 helper warps; infos and
//     attention+head fused.
// ============================================================
#define NB   4
#define NTH  512
#define BST  240
#define HST  108
#define SST  104

#define OFF_AHI 0                          // 80*240  = 19200
#define OFF_ALO 19200                      // 19200
#define OFF_BHI 38400                      // 112*240 = 26880
#define OFF_H   65280                      // 80*108*4 = 34560
#define OFF_W   99840                      // 40000
#define OFF_WM  139840                     // 8320
#define OFF_VW  148160                     // 8320
#define OFF_S   156480                     // 3328
#define OFF_SSW 159808                     // 1664
#define OFF_G   161472                     // 320
#define OFF_GP  161792                     // 640
#define OFF_F   162432                     // 4000
#define SCAN_SMEM 166432

__global__ __launch_bounds__(NTH, 1) void scan_mma_kernel(
    const float* __restrict__ U_w, const float* __restrict__ V_w,
    const float* __restrict__ W_w, const float* __restrict__ w_mem,
    const float* __restrict__ h0,  const float* __restrict__ a_dm_p,
    const float* __restrict__ in_data, const float* __restrict__ f_w,
    const float* __restrict__ H_w, const float* __restrict__ H_b,
    const float* __restrict__ a_out_p)
{
    extern __shared__ char smc[];
    float* sH  = (float*)(smc + OFF_H);
    float* sW  = (float*)(smc + OFF_W);
    float* sWm = (float*)(smc + OFF_WM);
    float* sVw = (float*)(smc + OFF_VW);
    float* sS  = (float*)(smc + OFF_S);
    float* sSW = (float*)(smc + OFF_SSW);
    float* sG  = (float*)(smc + OFF_G);
    float* sGp = (float*)(smc + OFF_GP);
    float* sF  = (float*)(smc + OFF_F);

    const int tid = threadIdx.x;
    const int w = tid >> 5;
    const int lane = tid & 31;
    const int b0g = blockIdx.x * NB;
    const float adm = *a_dm_p;
    const uint32_t smb = smem_u32(smc);

    // ---- zero A+B tiles (pad rows/cols must stay zero) ----
    for (int i = tid; i < OFF_H / 4; i += NTH) ((uint32_t*)smc)[i] = 0;
    __syncthreads();

    // ---- stage U (fp16), W, w_mem, f, h init + A tiles from h0 ----
    for (int i = tid; i < E_ * 50; i += NTH) {
        int f_ = i / 50, p = i % 50;
        float2 uv = *(const float2*)(U_w + f_ * E_ + 2 * p);
        __half2 uh = __floats2half2_rn(uv.x, uv.y);
        *(uint32_t*)(smc + OFF_BHI + f_ * BST + p * 4) = *reinterpret_cast<uint32_t*>(&uh);
    }
    for (int i = tid; i < E_ * E_; i += NTH) sW[i] = W_w[i];
    for (int i = tid; i < L_ * E_; i += NTH) sF[i] = f_w[i];
    for (int i = tid; i < N_ * E_; i += NTH) {
        int n_ = i / E_, e_ = i % E_;
        sWm[n_ * SST + e_] = w_mem[i];
    }
    for (int i = tid; i < 80 * 50; i += NTH) {
        int row = i / 50, p = i % 50;
        float2 hv = *(const float2*)(h0 + (row % N_) * E_ + 2 * p);
        *(float2*)(sH + row * HST + 2 * p) = hv;
        uint32_t hi, lo;
        split2h(hv.x, hv.y, hi, lo);
        *(uint32_t*)(smc + OFF_AHI + row * BST + p * 4) = hi;
        *(uint32_t*)(smc + OFF_ALO + row * BST + p * 4) = lo;
    }
    if (tid < 80) { sGp[2 * tid] = 1.f; sGp[2 * tid + 1] = 0.f; }
    __syncthreads();
    // Vw[n][f] = w_mem[n] . V_w[f] (one-time)
    for (int i = tid; i < N_ * E_; i += NTH) {
        int n_ = i / E_, f_ = i % E_;
        float acc = 0.f;
        for (int e_ = 0; e_ < E_; e_++) acc += sWm[n_ * SST + e_] * V_w[f_ * E_ + e_];
        sVw[n_ * SST + f_] = acc;
    }
    // s_0 = infos(t=0)
    for (int i = tid; i < NB * E_; i += NTH) {
        int bi = i / E_, e_ = i % E_;
        const float* ip = in_data + (long)(b0g + bi) * T_ * E_ + e_;
        float acc = 0.f;
#pragma unroll
        for (int l = 0; l < L_; l++) acc += sF[l * E_ + e_] * ip[(long)l * E_];
        sS[bi * SST + e_] = acc;
    }
    __syncthreads();

    const int stripe = w >> 1, nh = w & 1;
    const int m0 = stripe * 16;
    const int qr = lane >> 2, qc = lane & 3;
    const int r0 = m0 + qr, r1 = r0 + 8;
    const int grp = lane >> 3, lr = lane & 7;

    const int pf0 = tid - 320;
    const int pf1 = pf0 + 192;
    const int pf2 = pf0 + 384;
    const bool pfh2 = (pf0 >= 0) && (pf2 < NB * E_);

    for (int t = 0; t < NCH; t++) {
        const float* sScur = sS + (t & 1) * NB * SST;

        float acc[7][4];
        float inv0 = 0.f, inv1 = 0.f;
        float v0[10], v1[10], v2[10];

        // ================= phase A: fp16x2 MMA | helpers ==================
        if (w < 10) {
            inv0 = rsqrtf(sGp[2 * r0] + sGp[2 * r0 + 1]);
            inv1 = rsqrtf(sGp[2 * r1] + sGp[2 * r1 + 1]);
#pragma unroll
            for (int j = 0; j < 7; j++)
#pragma unroll
                for (int q = 0; q < 4; q++) acc[j][q] = 0.f;
            const uint32_t aBase = smb + OFF_AHI;
            const uint32_t bhBase = smb + OFF_BHI;
#pragma unroll
            for (int k = 0; k < 7; k++) {
                uint32_t ah[4], al[4];
                uint32_t aaddr = aBase + (uint32_t)((m0 + lr + ((grp & 1) << 3)) * BST
                               + k * 32 + ((grp >> 1) << 4));
                ldsm4(ah, aaddr);
                ldsm4(al, aaddr + 19200u);
                uint32_t bh[14];
#pragma unroll
                for (int pq = 0; pq < 3; pq++) {
                    int t0 = nh * 7 + pq * 2;
                    uint32_t addr = bhBase + (uint32_t)((t0 * 8 + lr + (grp >> 1) * 8) * BST
                                  + k * 32 + (grp & 1) * 16);
                    ldsm4(&bh[pq * 4], addr);
                }
#pragma unroll
                for (int j = 0; j < 6; j++) {
                    mma16816h(acc[j], ah, &bh[2 * j]);
                    mma16816h(acc[j], al, &bh[2 * j]);
                }
                if (nh == 0) {   // tail tile j=6 (cols 48-55)
                    uint32_t addr = bhBase + (uint32_t)((6 * 8 + lr) * BST
                                  + k * 32 + ((lane >> 3) & 1) * 16);
                    uint32_t bht[2];
                    ldsm2(bht, addr);
                    mma16816h(acc[6], ah, bht);
                    mma16816h(acc[6], al, bht);
                }
            }
        } else {
            if (t + 1 < NCH) {
                int bi0 = pf0 / E_, e0 = pf0 % E_;
                int bi1 = pf1 / E_, e1 = pf1 % E_;
                const float* ip0 = in_data + ((long)(b0g + bi0) * T_ + (t + 1) * L_) * E_ + e0;
                const float* ip1 = in_data + ((long)(b0g + bi1) * T_ + (t + 1) * L_) * E_ + e1;
#pragma unroll
                for (int l = 0; l < L_; l++) v0[l] = ip0[(long)l * E_];
#pragma unroll
                for (int l = 0; l < L_; l++) v1[l] = ip1[(long)l * E_];
                if (pfh2) {
                    int bi2 = pf2 / E_, e2 = pf2 % E_;
                    const float* ip2 = in_data + ((long)(b0g + bi2) * T_ + (t + 1) * L_) * E_ + e2;
#pragma unroll
                    for (int l = 0; l < L_; l++) v2[l] = ip2[(long)l * E_];
                }
            }
            int i = pf0;
            if (i < 100) {
                int f_ = i;
                float a0 = 0.f, a1 = 0.f, a2 = 0.f, a3 = 0.f;
                const float* wp = sW + f_ * E_;
                for (int e4 = 0; e4 < 25; e4++) {
                    float4 wv = *(const float4*)(wp + e4 * 4);
                    float4 s0 = *(const float4*)(sScur + 0 * SST + e4 * 4);
                    float4 s1 = *(const float4*)(sScur + 1 * SST + e4 * 4);
                    float4 s2 = *(const float4*)(sScur + 2 * SST + e4 * 4);
                    float4 s3 = *(const float4*)(sScur + 3 * SST + e4 * 4);
                    a0 += wv.x * s0.x + wv.y * s0.y + wv.z * s0.z + wv.w * s0.w;
                    a1 += wv.x * s1.x + wv.y * s1.y + wv.z * s1.z + wv.w * s1.w;
                    a2 += wv.x * s2.x + wv.y * s2.y + wv.z * s2.z + wv.w * s2.w;
                    a3 += wv.x * s3.x + wv.y * s3.y + wv.z * s3.z + wv.w * s3.w;
                }
                sSW[0 * SST + f_] = a0;
                sSW[1 * SST + f_] = a1;
                sSW[2 * SST + f_] = a2;
                sSW[3 * SST + f_] = a3;
            } else if (i < 180) {
                int row = i - 100;
                int bi = row / N_, ne = row % N_;
                const float* hp = sH + row * HST;
                const float* wp = sWm + ne * SST;
                const float* sp = sScur + bi * SST;
                float hs = 0.f, ws = 0.f;
                for (int e4 = 0; e4 < 25; e4++) {
                    float4 hv = *(const float4*)(hp + e4 * 4);
                    float4 wv = *(const float4*)(wp + e4 * 4);
                    float4 sv = *(const float4*)(sp + e4 * 4);
                    hs += hv.x * sv.x + hv.y * sv.y + hv.z * sv.z + hv.w * sv.w;
                    ws += wv.x * sv.x + wv.y * sv.y + wv.z * sv.z + wv.w * sv.w;
                }
                float inv = rsqrtf(sGp[2 * row] + sGp[2 * row + 1]);
                sG[row] = 1.f / (1.f + expf(-(inv * hs + ws)));
            }
        }
        __syncthreads();

        // ================= phase B: epilogue + A-tile store ===============
        if (w < 10) {
            float g0 = sG[r0], g1 = sG[r1];
            int bi0 = r0 / N_, ne0 = r0 % N_;
            int bi1 = r1 / N_, ne1 = r1 % N_;
            float ssq0 = 0.f, ssq1 = 0.f;
#pragma unroll
            for (int j = 0; j < 7; j++) {
                int f0 = (nh * 7 + j) * 8 + 2 * qc;
                if (f0 < 100) {
                    float2 vw0 = *(const float2*)(sVw + ne0 * SST + f0);
                    float2 sw0 = *(const float2*)(sSW + bi0 * SST + f0);
                    float2 hv0 = *(const float2*)(sH + r0 * HST + f0);
                    float c0 = acc[j][0] * inv0 + vw0.x + sw0.x;
                    float c1 = acc[j][1] * inv0 + vw0.y + sw0.y;
                    c0 = (c0 >= 0.f) ? c0 : adm * c0;
                    c1 = (c1 >= 0.f) ? c1 : adm * c1;
                    float n0v = hv0.x * inv0 + g0 * c0;
                    float n1v = hv0.y * inv0 + g0 * c1;
                    *(float2*)(sH + r0 * HST + f0) = make_float2(n0v, n1v);
                    ssq0 += n0v * n0v + n1v * n1v;
                    uint32_t hi0, lo0;
                    split2h(n0v, n1v, hi0, lo0);
                    *(uint32_t*)(smc + OFF_AHI + r0 * BST + f0 * 2) = hi0;
                    *(uint32_t*)(smc + OFF_ALO + r0 * BST + f0 * 2) = lo0;

                    float2 vw1 = *(const float2*)(sVw + ne1 * SST + f0);
                    float2 sw1 = *(const float2*)(sSW + bi1 * SST + f0);
                    float2 hv1 = *(const float2*)(sH + r1 * HST + f0);
                    float d0 = acc[j][2] * inv1 + vw1.x + sw1.x;
                    float d1 = acc[j][3] * inv1 + vw1.y + sw1.y;
                    d0 = (d0 >= 0.f) ? d0 : adm * d0;
                    d1 = (d1 >= 0.f) ? d1 : adm * d1;
                    float m0v = hv1.x * inv1 + g1 * d0;
                    float m1v = hv1.y * inv1 + g1 * d1;
                    *(float2*)(sH + r1 * HST + f0) = make_float2(m0v, m1v);
                    ssq1 += m0v * m0v + m1v * m1v;
                    uint32_t hi1, lo1;
                    split2h(m0v, m1v, hi1, lo1);
                    *(uint32_t*)(smc + OFF_AHI + r1 * BST + f0 * 2) = hi1;
                    *(uint32_t*)(smc + OFF_ALO + r1 * BST + f0 * 2) = lo1;
                }
            }
            ssq0 += __shfl_xor_sync(0xffffffffu, ssq0, 1);
            ssq0 += __shfl_xor_sync(0xffffffffu, ssq0, 2);
            ssq1 += __shfl_xor_sync(0xffffffffu, ssq1, 1);
            ssq1 += __shfl_xor_sync(0xffffffffu, ssq1, 2);
            if (qc == 0) {
                sGp[2 * r0 + nh] = ssq0;
                sGp[2 * r1 + nh] = ssq1;
            }
        } else if (t + 1 < NCH) {
            float* sNxt = sS + ((t + 1) & 1) * NB * SST;
            int bi0 = pf0 / E_, e0 = pf0 % E_;
            int bi1 = pf1 / E_, e1 = pf1 % E_;
            float a = 0.f, b = 0.f;
#pragma unroll
            for (int l = 0; l < L_; l++) a += sF[l * E_ + e0] * v0[l];
#pragma unroll
            for (int l = 0; l < L_; l++) b += sF[l * E_ + e1] * v1[l];
            sNxt[bi0 * SST + e0] = a;
            sNxt[bi1 * SST + e1] = b;
            if (pfh2) {
                int bi2 = pf2 / E_, e2 = pf2 % E_;
                float c = 0.f;
#pragma unroll
                for (int l = 0; l < L_; l++) c += sF[l * E_ + e2] * v2[l];
                sNxt[bi2 * SST + e2] = c;
            }
        }
        __syncthreads();
    }

    // ================= fused attention + head ==========================
    if (tid < 80) sG[tid] = rsqrtf(sGp[2 * tid] + sGp[2 * tid + 1]);
    __syncthreads();
    for (int i = tid; i < 80 * E_; i += NTH) {
        int row = i / E_, e_ = i % E_;
        sH[row * HST + e_] *= sG[row];
    }
    {
        float* sQ = sS;
        for (int i = tid; i < NB * E_; i += NTH) {
            int bi = i / E_, e_ = i % E_;
            const float* ip = in_data + ((long)(b0g + bi) * T_ + NCH * L_) * E_ + e_;
            float acc = 0.f;
#pragma unroll
            for (int l = 0; l < REST; l++) acc += sF[l * E_ + e_] * ip[(long)l * E_];
            sQ[bi * SST + e_] = acc;
        }
    }
    for (int i = tid; i < E_ * E_; i += NTH) sW[i] = H_w[i];
    __syncthreads();
    if (tid < 80) {
        int bi = tid / N_;
        const float* hp = sH + tid * HST;
        const float* qp = sS + bi * SST;
        float d = 0.f;
        for (int e4 = 0; e4 < 25; e4++) {
            float4 hv = *(const float4*)(hp + e4 * 4);
            float4 qv = *(const float4*)(qp + e4 * 4);
            d += hv.x * qv.x + hv.y * qv.y + hv.z * qv.z + hv.w * qv.w;
        }
        sGp[tid] = d;
    }
    __syncthreads();
    if (tid < NB) {
        const float* lp = sGp + tid * N_;
        float m = lp[0];
        for (int n = 1; n < N_; n++) m = fmaxf(m, lp[n]);
        float s = 0.f;
        float* pp = sG + tid * N_;
        for (int n = 0; n < N_; n++) { float ev = expf(lp[n] - m); pp[n] = ev; s += ev; }
        float inv = 1.f / s;
        for (int n = 0; n < N_; n++) pp[n] *= inv;
    }
    __syncthreads();
    {
        float* sU = sS + NB * SST;
        for (int i = tid; i < NB * E_; i += NTH) {
            int bi = i / E_, e_ = i % E_;
            float u = 0.f;
#pragma unroll
            for (int n = 0; n < N_; n++) u += sG[bi * N_ + n] * sH[(bi * N_ + n) * HST + e_];
            sU[bi * SST + e_] = u;
        }
    }
    __syncthreads();
    {
        const float* sQ = sS;
        const float* sU = sS + NB * SST;
        float ao = *a_out_p;
        for (int i = tid; i < NB * E_; i += NTH) {
            int bi = i / E_, f_ = i % E_;
            float acc = sQ[bi * SST + f_] + H_b[f_];
            const float* hw = sW + f_ * E_;
            const float* up = sU + bi * SST;
            for (int e4 = 0; e4 < 25; e4++) {
                float4 hv = *(const float4*)(hw + e4 * 4);
                float4 uv = *(const float4*)(up + e4 * 4);
                acc += hv.x * uv.x + hv.y * uv.y + hv.z * uv.z + hv.w * uv.w;
            }
            g_ya[(long)(b0g + bi) * E_ + f_] = (acc >= 0.f) ? acc : ao * acc;
        }
    }
}

// ============================================================
// K3: convert R_w and g_ya into packed bf16 hi/lo pair rows
// ============================================================
__global__ void convert_kernel(const float* __restrict__ R_w) {
    int idx = blockIdx.x * 256 + threadIdx.x;
    const int RTOT = V_ * 60;
    if (idx < RTOT) {
        int v = idx / 60, p = idx % 60;
        uint32_t hi = 0, lo = 0;
        if (p < 50) {
            float2 rv = *(const float2*)(R_w + (long)v * E_ + 2 * p);
            split2(rv.x, rv.y, hi, lo);
        }
        g_Rhi[idx] = hi;
        g_Rlo[idx] = lo;
    } else if (idx < RTOT + B_ * 60) {
        int i = idx - RTOT;
        int b = i / 60, p = i % 60;
        uint32_t hi = 0, lo = 0;
        if (p < 50) {
            float2 yv = *(const float2*)(g_ya + (long)b * E_ + 2 * p);
            split2(yv.x, yv.y, hi, lo);
        }
        g_Yhi[i] = hi;
        g_Ylo[i] = lo;
    }
}

// ============================================================
// K4: out = ya @ R_w^T + R_b on HMMA (bf16x3). 128b x 128v tiles.
// ============================================================
#define O_AHI 0
#define O_ALO 30720
#define O_BHI 61440
#define O_BLO 92160
#define OUT_SMEM 122880

__global__ __launch_bounds__(256, 1) void out_mma_kernel(
    const float* __restrict__ R_b, float* __restrict__ out)
{
    extern __shared__ char smo[];
    const int tid = threadIdx.x;
    const int w = tid >> 5;
    const int lane = tid & 31;
    const int v0 = blockIdx.x * 128;
    const int b0 = blockIdx.y * 128;
    const uint32_t smb = smem_u32(smo);

    uint32_t* sAhi = (uint32_t*)(smo + O_AHI);
    uint32_t* sAlo = (uint32_t*)(smo + O_ALO);
    uint32_t* sBhi = (uint32_t*)(smo + O_BHI);
    uint32_t* sBlo = (uint32_t*)(smo + O_BLO);
    for (int i = tid; i < 128 * 60; i += 256) {
        int r = i / 60, p = i % 60;
        sAhi[i] = g_Yhi[(b0 + r) * 60 + p];
        sAlo[i] = g_Ylo[(b0 + r) * 60 + p];
        sBhi[i] = g_Rhi[(long)(v0 + r) * 60 + p];
        sBlo[i] = g_Rlo[(long)(v0 + r) * 60 + p];
    }
    __syncthreads();

    const int mw = w >> 1, nw = w & 1;
    const int m0 = mw * 32;
    const int n0 = nw * 64;
    const int qr = lane >> 2, qc = lane & 3;
    const int grp = lane >> 3, lr = lane & 7;

    float acc[2][8][4];
#pragma unroll
    for (int mh = 0; mh < 2; mh++)
#pragma unroll
        for (int j = 0; j < 8; j++)
#pragma unroll
            for (int q = 0; q < 4; q++) acc[mh][j][q] = 0.f;

#pragma unroll
    for (int k = 0; k < 7; k++) {
        uint32_t ah[2][4], al[2][4];
#pragma unroll
        for (int mh = 0; mh < 2; mh++) {
            uint32_t aaddr = smb + O_AHI + (uint32_t)((m0 + 16 * mh + lr + ((grp & 1) << 3)) * 240
                           + k * 32 + ((grp >> 1) << 4));
            ldsm4(ah[mh], aaddr);
            ldsm4(al[mh], aaddr + 30720u);
        }
#pragma unroll
        for (int pq = 0; pq < 4; pq++) {
            uint32_t addr = smb + O_BHI + (uint32_t)((n0 + pq * 16 + lr + (grp >> 1) * 8) * 240
                          + k * 32 + (grp & 1) * 16);
            uint32_t bh[4], bl[4];
            ldsm4(bh, addr);
            ldsm4(bl, addr + 30720u);
#pragma unroll
            for (int mh = 0; mh < 2; mh++)
#pragma unroll
                for (int jj = 0; jj < 2; jj++) {
                    int j = pq * 2 + jj;
                    mma16816(acc[mh][j], ah[mh], &bh[2 * jj]);
                    mma16816(acc[mh][j], al[mh], &bh[2 * jj]);
                    mma16816(acc[mh][j], ah[mh], &bl[2 * jj]);
                }
        }
    }

#pragma unroll
    for (int mh = 0; mh < 2; mh++) {
        int ra = b0 + m0 + 16 * mh + qr;
        int rb2 = ra + 8;
#pragma unroll
        for (int j = 0; j < 8; j++) {
            int c = v0 + n0 + j * 8 + 2 * qc;
            float2 rb = *(const float2*)(R_b + c);
            float2 o0 = make_float2(acc[mh][j][0] + rb.x, acc[mh][j][1] + rb.y);
            float2 o1 = make_float2(acc[mh][j][2] + rb.x, acc[mh][j][3] + rb.y);
            *(float2*)(out + (long)ra * V_ + c) = o0;
            *(float2*)(out + (long)rb2 * V_ + c) = o1;
        }
    }
}

// ============================================================
extern "C" void kernel_launch(void* const* d_in, const int* in_sizes, int n_in,
                              void* d_out, int out_size) {
    const float* in_data = (const float*)d_in[0];
    const float* f       = (const float*)d_in[1];
    const float* h0      = (const float*)d_in[2];
    const float* w_mem   = (const float*)d_in[3];
    const float* U_w     = (const float*)d_in[4];
    const float* V_w     = (const float*)d_in[5];
    const float* W_w     = (const float*)d_in[6];
    const float* a_dm    = (const float*)d_in[7];
    const float* H_w     = (const float*)d_in[8];
    const float* H_b     = (const float*)d_in[9];
    const float* R_w     = (const float*)d_in[10];
    const float* R_b     = (const float*)d_in[11];
    const float* a_out   = (const float*)d_in[12];
    float* out = (float*)d_out;

    cudaFuncSetAttribute(scan_mma_kernel, cudaFuncAttributeMaxDynamicSharedMemorySize,
                         SCAN_SMEM);
    cudaFuncSetAttribute(out_mma_kernel, cudaFuncAttributeMaxDynamicSharedMemorySize,
                         OUT_SMEM);

    scan_mma_kernel<<<B_ / NB, NTH, SCAN_SMEM>>>(U_w, V_w, W_w, w_mem, h0, a_dm,
                                                 in_data, f, H_w, H_b, a_out);
    const int conv_total = V_ * 60 + B_ * 60;
    convert_kernel<<<(conv_total + 255) / 256, 256>>>(R_w);
    dim3 g4(V_ / 128, B_ / 128);
    out_mma_kernel<<<g4, 256, OUT_SMEM>>>(R_b, out);
}

// round 13
// speedup vs baseline: 1.5247x; 1.0637x over previous
#include <cuda_runtime.h>
#include <cuda_bf16.h>
#include <cuda_fp16.h>
#include <math.h>
#include <stdint.h>

#define B_   512
#define T_   1005
#define E_   100
#define L_   10
#define N_   20
#define V_   32000
#define NCH  100      // n_full = T/L
#define REST 5        // T % L

// ---- scratch (no allocations allowed) ----
__device__ float g_ya[B_ * E_];                 // prelu(y)
__device__ uint32_t g_Rhi[V_ * 60];             // R_w bf16-hi pairs, 240B rows
__device__ uint32_t g_Rlo[V_ * 60];
__device__ uint32_t g_Yhi[B_ * 60];             // ya bf16-hi pairs
__device__ uint32_t g_Ylo[B_ * 60];

// ---- warp MMA helpers (portable PTX, sm_80+) ----
__device__ __forceinline__ uint32_t smem_u32(const void* p) {
    uint32_t a;
    asm("{ .reg .u64 t; cvta.to.shared.u64 t, %1; cvt.u32.u64 %0, t; }"
        : "=r"(a) : "l"(p));
    return a;
}
__device__ __forceinline__ void ldsm4(uint32_t* r, uint32_t a) {
    asm volatile("ldmatrix.sync.aligned.m8n8.x4.shared.b16 {%0,%1,%2,%3}, [%4];"
        : "=r"(r[0]), "=r"(r[1]), "=r"(r[2]), "=r"(r[3]) : "r"(a));
}
__device__ __forceinline__ void ldsm2(uint32_t* r, uint32_t a) {
    asm volatile("ldmatrix.sync.aligned.m8n8.x2.shared.b16 {%0,%1}, [%2];"
        : "=r"(r[0]), "=r"(r[1]) : "r"(a));
}
// bf16 MMA (out GEMM)
__device__ __forceinline__ void mma16816(float* c, const uint32_t* a, const uint32_t* b) {
    asm volatile(
        "mma.sync.aligned.m16n8k16.row.col.f32.bf16.bf16.f32 "
        "{%0,%1,%2,%3}, {%4,%5,%6,%7}, {%8,%9}, {%0,%1,%2,%3};"
        : "+f"(c[0]), "+f"(c[1]), "+f"(c[2]), "+f"(c[3])
        : "r"(a[0]), "r"(a[1]), "r"(a[2]), "r"(a[3]), "r"(b[0]), "r"(b[1]));
}
// fp16 MMA (scan GEMM)
__device__ __forceinline__ void mma16816h(float* c, const uint32_t* a, const uint32_t* b) {
    asm volatile(
        "mma.sync.aligned.m16n8k16.row.col.f32.f16.f16.f32 "
        "{%0,%1,%2,%3}, {%4,%5,%6,%7}, {%8,%9}, {%0,%1,%2,%3};"
        : "+f"(c[0]), "+f"(c[1]), "+f"(c[2]), "+f"(c[3])
        : "r"(a[0]), "r"(a[1]), "r"(a[2]), "r"(a[3]), "r"(b[0]), "r"(b[1]));
}
// split two fp32 into packed bf16 hi + residual lo (out GEMM convert)
__device__ __forceinline__ void split2(float x0, float x1, uint32_t& hi, uint32_t& lo) {
    __nv_bfloat162 bh = __floats2bfloat162_rn(x0, x1);
    uint32_t h = *reinterpret_cast<uint32_t*>(&bh);
    float hf0 = __uint_as_float(h << 16);
    float hf1 = __uint_as_float(h & 0xffff0000u);
    __nv_bfloat162 bl = __floats2bfloat162_rn(x0 - hf0, x1 - hf1);
    hi = h;
    lo = *reinterpret_cast<uint32_t*>(&bl);
}
// pack two fp32 into fp16x2
__device__ __forceinline__ uint32_t pack_h2(float x0, float x1) {
    __half2 h2 = __floats2half2_rn(x0, x1);
    return *reinterpret_cast<uint32_t*>(&h2);
}

// ============================================================
// K2: persistent scan on warp MMA (plain fp16 HMMA).
//     128 CTAs x 4 batches; 10 MMA + 6 helper warps; infos and
//     attention+head fused.
// ============================================================
#define NB   4
#define NTH  512
#define BST  240
#define HST  108
#define SST  104

#define OFF_AHI 0                          // 80*240  = 19200
#define OFF_BHI 19200                      // 112*240 = 26880
#define OFF_H   46080                      // 34560
#define OFF_W   80640                      // 40000
#define OFF_WM  120640                     // 8320
#define OFF_VW  128960                     // 8320
#define OFF_S   137280                     // 3328
#define OFF_SSW 140608                     // 1664
#define OFF_G   142272                     // 320
#define OFF_GP  142592                     // 640
#define OFF_F   143232                     // 4000
#define SCAN_SMEM 147232

__global__ __launch_bounds__(NTH, 1) void scan_mma_kernel(
    const float* __restrict__ U_w, const float* __restrict__ V_w,
    const float* __restrict__ W_w, const float* __restrict__ w_mem,
    const float* __restrict__ h0,  const float* __restrict__ a_dm_p,
    const float* __restrict__ in_data, const float* __restrict__ f_w,
    const float* __restrict__ H_w, const float* __restrict__ H_b,
    const float* __restrict__ a_out_p)
{
    extern __shared__ char smc[];
    float* sH  = (float*)(smc + OFF_H);
    float* sW  = (float*)(smc + OFF_W);
    float* sWm = (float*)(smc + OFF_WM);
    float* sVw = (float*)(smc + OFF_VW);
    float* sS  = (float*)(smc + OFF_S);
    float* sSW = (float*)(smc + OFF_SSW);
    float* sG  = (float*)(smc + OFF_G);
    float* sGp = (float*)(smc + OFF_GP);
    float* sF  = (float*)(smc + OFF_F);

    const int tid = threadIdx.x;
    const int w = tid >> 5;
    const int lane = tid & 31;
    const int b0g = blockIdx.x * NB;
    const float adm = *a_dm_p;
    const uint32_t smb = smem_u32(smc);

    // ---- zero A+B tiles (pad rows/cols must stay zero) ----
    for (int i = tid; i < OFF_H / 4; i += NTH) ((uint32_t*)smc)[i] = 0;
    __syncthreads();

    // ---- stage U (fp16), W, w_mem, f, h init + A tile from h0 ----
    for (int i = tid; i < E_ * 50; i += NTH) {
        int f_ = i / 50, p = i % 50;
        float2 uv = *(const float2*)(U_w + f_ * E_ + 2 * p);
        *(uint32_t*)(smc + OFF_BHI + f_ * BST + p * 4) = pack_h2(uv.x, uv.y);
    }
    for (int i = tid; i < E_ * E_; i += NTH) sW[i] = W_w[i];
    for (int i = tid; i < L_ * E_; i += NTH) sF[i] = f_w[i];
    for (int i = tid; i < N_ * E_; i += NTH) {
        int n_ = i / E_, e_ = i % E_;
        sWm[n_ * SST + e_] = w_mem[i];
    }
    for (int i = tid; i < 80 * 50; i += NTH) {
        int row = i / 50, p = i % 50;
        float2 hv = *(const float2*)(h0 + (row % N_) * E_ + 2 * p);
        *(float2*)(sH + row * HST + 2 * p) = hv;
        *(uint32_t*)(smc + OFF_AHI + row * BST + p * 4) = pack_h2(hv.x, hv.y);
    }
    if (tid < 80) { sGp[2 * tid] = 1.f; sGp[2 * tid + 1] = 0.f; }
    __syncthreads();
    // Vw[n][f] = w_mem[n] . V_w[f] (one-time)
    for (int i = tid; i < N_ * E_; i += NTH) {
        int n_ = i / E_, f_ = i % E_;
        float acc = 0.f;
        for (int e_ = 0; e_ < E_; e_++) acc += sWm[n_ * SST + e_] * V_w[f_ * E_ + e_];
        sVw[n_ * SST + f_] = acc;
    }
    // s_0 = infos(t=0)
    for (int i = tid; i < NB * E_; i += NTH) {
        int bi = i / E_, e_ = i % E_;
        const float* ip = in_data + (long)(b0g + bi) * T_ * E_ + e_;
        float acc = 0.f;
#pragma unroll
        for (int l = 0; l < L_; l++) acc += sF[l * E_ + e_] * ip[(long)l * E_];
        sS[bi * SST + e_] = acc;
    }
    __syncthreads();

    const int stripe = w >> 1, nh = w & 1;
    const int m0 = stripe * 16;
    const int qr = lane >> 2, qc = lane & 3;
    const int r0 = m0 + qr, r1 = r0 + 8;
    const int grp = lane >> 3, lr = lane & 7;

    const int pf0 = tid - 320;
    const int pf1 = pf0 + 192;
    const int pf2 = pf0 + 384;
    const bool pfh2 = (pf0 >= 0) && (pf2 < NB * E_);

    for (int t = 0; t < NCH; t++) {
        const float* sScur = sS + (t & 1) * NB * SST;

        float acc[7][4];
        float inv0 = 0.f, inv1 = 0.f;
        float v0[10], v1[10], v2[10];

        // ================= phase A: fp16 MMA | helpers ====================
        if (w < 10) {
            inv0 = rsqrtf(sGp[2 * r0] + sGp[2 * r0 + 1]);
            inv1 = rsqrtf(sGp[2 * r1] + sGp[2 * r1 + 1]);
#pragma unroll
            for (int j = 0; j < 7; j++)
#pragma unroll
                for (int q = 0; q < 4; q++) acc[j][q] = 0.f;
            const uint32_t aBase = smb + OFF_AHI;
            const uint32_t bhBase = smb + OFF_BHI;
#pragma unroll
            for (int k = 0; k < 7; k++) {
                uint32_t ah[4];
                uint32_t aaddr = aBase + (uint32_t)((m0 + lr + ((grp & 1) << 3)) * BST
                               + k * 32 + ((grp >> 1) << 4));
                ldsm4(ah, aaddr);
                uint32_t bh[14];
#pragma unroll
                for (int pq = 0; pq < 3; pq++) {
                    int t0 = nh * 7 + pq * 2;
                    uint32_t addr = bhBase + (uint32_t)((t0 * 8 + lr + (grp >> 1) * 8) * BST
                                  + k * 32 + (grp & 1) * 16);
                    ldsm4(&bh[pq * 4], addr);
                }
#pragma unroll
                for (int j = 0; j < 6; j++) {
                    mma16816h(acc[j], ah, &bh[2 * j]);
                }
                if (nh == 0) {   // tail tile j=6 (cols 48-55)
                    uint32_t addr = bhBase + (uint32_t)((6 * 8 + lr) * BST
                                  + k * 32 + ((lane >> 3) & 1) * 16);
                    uint32_t bht[2];
                    ldsm2(bht, addr);
                    mma16816h(acc[6], ah, bht);
                }
            }
        } else {
            if (t + 1 < NCH) {
                int bi0 = pf0 / E_, e0 = pf0 % E_;
                int bi1 = pf1 / E_, e1 = pf1 % E_;
                const float* ip0 = in_data + ((long)(b0g + bi0) * T_ + (t + 1) * L_) * E_ + e0;
                const float* ip1 = in_data + ((long)(b0g + bi1) * T_ + (t + 1) * L_) * E_ + e1;
#pragma unroll
                for (int l = 0; l < L_; l++) v0[l] = ip0[(long)l * E_];
#pragma unroll
                for (int l = 0; l < L_; l++) v1[l] = ip1[(long)l * E_];
                if (pfh2) {
                    int bi2 = pf2 / E_, e2 = pf2 % E_;
                    const float* ip2 = in_data + ((long)(b0g + bi2) * T_ + (t + 1) * L_) * E_ + e2;
#pragma unroll
                    for (int l = 0; l < L_; l++) v2[l] = ip2[(long)l * E_];
                }
            }
            int i = pf0;
            if (i < 100) {
                int f_ = i;
                float a0 = 0.f, a1 = 0.f, a2 = 0.f, a3 = 0.f;
                const float* wp = sW + f_ * E_;
                for (int e4 = 0; e4 < 25; e4++) {
                    float4 wv = *(const float4*)(wp + e4 * 4);
                    float4 s0 = *(const float4*)(sScur + 0 * SST + e4 * 4);
                    float4 s1 = *(const float4*)(sScur + 1 * SST + e4 * 4);
                    float4 s2 = *(const float4*)(sScur + 2 * SST + e4 * 4);
                    float4 s3 = *(const float4*)(sScur + 3 * SST + e4 * 4);
                    a0 += wv.x * s0.x + wv.y * s0.y + wv.z * s0.z + wv.w * s0.w;
                    a1 += wv.x * s1.x + wv.y * s1.y + wv.z * s1.z + wv.w * s1.w;
                    a2 += wv.x * s2.x + wv.y * s2.y + wv.z * s2.z + wv.w * s2.w;
                    a3 += wv.x * s3.x + wv.y * s3.y + wv.z * s3.z + wv.w * s3.w;
                }
                sSW[0 * SST + f_] = a0;
                sSW[1 * SST + f_] = a1;
                sSW[2 * SST + f_] = a2;
                sSW[3 * SST + f_] = a3;
            } else if (i < 180) {
                int row = i - 100;
                int bi = row / N_, ne = row % N_;
                const float* hp = sH + row * HST;
                const float* wp = sWm + ne * SST;
                const float* sp = sScur + bi * SST;
                float hs = 0.f, ws = 0.f;
                for (int e4 = 0; e4 < 25; e4++) {
                    float4 hv = *(const float4*)(hp + e4 * 4);
                    float4 wv = *(const float4*)(wp + e4 * 4);
                    float4 sv = *(const float4*)(sp + e4 * 4);
                    hs += hv.x * sv.x + hv.y * sv.y + hv.z * sv.z + hv.w * sv.w;
                    ws += wv.x * sv.x + wv.y * sv.y + wv.z * sv.z + wv.w * sv.w;
                }
                float inv = rsqrtf(sGp[2 * row] + sGp[2 * row + 1]);
                sG[row] = 1.f / (1.f + expf(-(inv * hs + ws)));
            }
        }
        __syncthreads();

        // ================= phase B: epilogue + A-tile store ===============
        if (w < 10) {
            float g0 = sG[r0], g1 = sG[r1];
            int bi0 = r0 / N_, ne0 = r0 % N_;
            int bi1 = r1 / N_, ne1 = r1 % N_;
            float ssq0 = 0.f, ssq1 = 0.f;
#pragma unroll
            for (int j = 0; j < 7; j++) {
                int f0 = (nh * 7 + j) * 8 + 2 * qc;
                if (f0 < 100) {
                    float2 vw0 = *(const float2*)(sVw + ne0 * SST + f0);
                    float2 sw0 = *(const float2*)(sSW + bi0 * SST + f0);
                    float2 hv0 = *(const float2*)(sH + r0 * HST + f0);
                    float c0 = acc[j][0] * inv0 + vw0.x + sw0.x;
                    float c1 = acc[j][1] * inv0 + vw0.y + sw0.y;
                    c0 = (c0 >= 0.f) ? c0 : adm * c0;
                    c1 = (c1 >= 0.f) ? c1 : adm * c1;
                    float n0v = hv0.x * inv0 + g0 * c0;
                    float n1v = hv0.y * inv0 + g0 * c1;
                    *(float2*)(sH + r0 * HST + f0) = make_float2(n0v, n1v);
                    ssq0 += n0v * n0v + n1v * n1v;
                    *(uint32_t*)(smc + OFF_AHI + r0 * BST + f0 * 2) = pack_h2(n0v, n1v);

                    float2 vw1 = *(const float2*)(sVw + ne1 * SST + f0);
                    float2 sw1 = *(const float2*)(sSW + bi1 * SST + f0);
                    float2 hv1 = *(const float2*)(sH + r1 * HST + f0);
                    float d0 = acc[j][2] * inv1 + vw1.x + sw1.x;
                    float d1 = acc[j][3] * inv1 + vw1.y + sw1.y;
                    d0 = (d0 >= 0.f) ? d0 : adm * d0;
                    d1 = (d1 >= 0.f) ? d1 : adm * d1;
                    float m0v = hv1.x * inv1 + g1 * d0;
                    float m1v = hv1.y * inv1 + g1 * d1;
                    *(float2*)(sH + r1 * HST + f0) = make_float2(m0v, m1v);
                    ssq1 += m0v * m0v + m1v * m1v;
                    *(uint32_t*)(smc + OFF_AHI + r1 * BST + f0 * 2) = pack_h2(m0v, m1v);
                }
            }
            ssq0 += __shfl_xor_sync(0xffffffffu, ssq0, 1);
            ssq0 += __shfl_xor_sync(0xffffffffu, ssq0, 2);
            ssq1 += __shfl_xor_sync(0xffffffffu, ssq1, 1);
            ssq1 += __shfl_xor_sync(0xffffffffu, ssq1, 2);
            if (qc == 0) {
                sGp[2 * r0 + nh] = ssq0;
                sGp[2 * r1 + nh] = ssq1;
            }
        } else if (t + 1 < NCH) {
            float* sNxt = sS + ((t + 1) & 1) * NB * SST;
            int bi0 = pf0 / E_, e0 = pf0 % E_;
            int bi1 = pf1 / E_, e1 = pf1 % E_;
            float a = 0.f, b = 0.f;
#pragma unroll
            for (int l = 0; l < L_; l++) a += sF[l * E_ + e0] * v0[l];
#pragma unroll
            for (int l = 0; l < L_; l++) b += sF[l * E_ + e1] * v1[l];
            sNxt[bi0 * SST + e0] = a;
            sNxt[bi1 * SST + e1] = b;
            if (pfh2) {
                int bi2 = pf2 / E_, e2 = pf2 % E_;
                float c = 0.f;
#pragma unroll
                for (int l = 0; l < L_; l++) c += sF[l * E_ + e2] * v2[l];
                sNxt[bi2 * SST + e2] = c;
            }
        }
        __syncthreads();
    }

    // ================= fused attention + head ==========================
    if (tid < 80) sG[tid] = rsqrtf(sGp[2 * tid] + sGp[2 * tid + 1]);
    __syncthreads();
    for (int i = tid; i < 80 * E_; i += NTH) {
        int row = i / E_, e_ = i % E_;
        sH[row * HST + e_] *= sG[row];
    }
    {
        float* sQ = sS;
        for (int i = tid; i < NB * E_; i += NTH) {
            int bi = i / E_, e_ = i % E_;
            const float* ip = in_data + ((long)(b0g + bi) * T_ + NCH * L_) * E_ + e_;
            float acc = 0.f;
#pragma unroll
            for (int l = 0; l < REST; l++) acc += sF[l * E_ + e_] * ip[(long)l * E_];
            sQ[bi * SST + e_] = acc;
        }
    }
    for (int i = tid; i < E_ * E_; i += NTH) sW[i] = H_w[i];
    __syncthreads();
    if (tid < 80) {
        int bi = tid / N_;
        const float* hp = sH + tid * HST;
        const float* qp = sS + bi * SST;
        float d = 0.f;
        for (int e4 = 0; e4 < 25; e4++) {
            float4 hv = *(const float4*)(hp + e4 * 4);
            float4 qv = *(const float4*)(qp + e4 * 4);
            d += hv.x * qv.x + hv.y * qv.y + hv.z * qv.z + hv.w * qv.w;
        }
        sGp[tid] = d;
    }
    __syncthreads();
    if (tid < NB) {
        const float* lp = sGp + tid * N_;
        float m = lp[0];
        for (int n = 1; n < N_; n++) m = fmaxf(m, lp[n]);
        float s = 0.f;
        float* pp = sG + tid * N_;
        for (int n = 0; n < N_; n++) { float ev = expf(lp[n] - m); pp[n] = ev; s += ev; }
        float inv = 1.f / s;
        for (int n = 0; n < N_; n++) pp[n] *= inv;
    }
    __syncthreads();
    {
        float* sU = sS + NB * SST;
        for (int i = tid; i < NB * E_; i += NTH) {
            int bi = i / E_, e_ = i % E_;
            float u = 0.f;
#pragma unroll
            for (int n = 0; n < N_; n++) u += sG[bi * N_ + n] * sH[(bi * N_ + n) * HST + e_];
            sU[bi * SST + e_] = u;
        }
    }
    __syncthreads();
    {
        const float* sQ = sS;
        const float* sU = sS + NB * SST;
        float ao = *a_out_p;
        for (int i = tid; i < NB * E_; i += NTH) {
            int bi = i / E_, f_ = i % E_;
            float acc = sQ[bi * SST + f_] + H_b[f_];
            const float* hw = sW + f_ * E_;
            const float* up = sU + bi * SST;
            for (int e4 = 0; e4 < 25; e4++) {
                float4 hv = *(const float4*)(hw + e4 * 4);
                float4 uv = *(const float4*)(up + e4 * 4);
                acc += hv.x * uv.x + hv.y * uv.y + hv.z * uv.z + hv.w * uv.w;
            }
            g_ya[(long)(b0g + bi) * E_ + f_] = (acc >= 0.f) ? acc : ao * acc;
        }
    }
}

// ============================================================
// K3: convert R_w and g_ya into packed bf16 hi/lo pair rows
// ============================================================
__global__ void convert_kernel(const float* __restrict__ R_w) {
    int idx = blockIdx.x * 256 + threadIdx.x;
    const int RTOT = V_ * 60;
    if (idx < RTOT) {
        int v = idx / 60, p = idx % 60;
        uint32_t hi = 0, lo = 0;
        if (p < 50) {
            float2 rv = *(const float2*)(R_w + (long)v * E_ + 2 * p);
            split2(rv.x, rv.y, hi, lo);
        }
        g_Rhi[idx] = hi;
        g_Rlo[idx] = lo;
    } else if (idx < RTOT + B_ * 60) {
        int i = idx - RTOT;
        int b = i / 60, p = i % 60;
        uint32_t hi = 0, lo = 0;
        if (p < 50) {
            float2 yv = *(const float2*)(g_ya + (long)b * E_ + 2 * p);
            split2(yv.x, yv.y, hi, lo);
        }
        g_Yhi[i] = hi;
        g_Ylo[i] = lo;
    }
}

// ============================================================
// K4: out = ya @ R_w^T + R_b on HMMA (bf16x3). 128b x 128v tiles.
// ============================================================
#define O_AHI 0
#define O_ALO 30720
#define O_BHI 61440
#define O_BLO 92160
#define OUT_SMEM 122880

__global__ __launch_bounds__(256, 1) void out_mma_kernel(
    const float* __restrict__ R_b, float* __restrict__ out)
{
    extern __shared__ char smo[];
    const int tid = threadIdx.x;
    const int w = tid >> 5;
    const int lane = tid & 31;
    const int v0 = blockIdx.x * 128;
    const int b0 = blockIdx.y * 128;
    const uint32_t smb = smem_u32(smo);

    uint32_t* sAhi = (uint32_t*)(smo + O_AHI);
    uint32_t* sAlo = (uint32_t*)(smo + O_ALO);
    uint32_t* sBhi = (uint32_t*)(smo + O_BHI);
    uint32_t* sBlo = (uint32_t*)(smo + O_BLO);
    for (int i = tid; i < 128 * 60; i += 256) {
        int r = i / 60, p = i % 60;
        sAhi[i] = g_Yhi[(b0 + r) * 60 + p];
        sAlo[i] = g_Ylo[(b0 + r) * 60 + p];
        sBhi[i] = g_Rhi[(long)(v0 + r) * 60 + p];
        sBlo[i] = g_Rlo[(long)(v0 + r) * 60 + p];
    }
    __syncthreads();

    const int mw = w >> 1, nw = w & 1;
    const int m0 = mw * 32;
    const int n0 = nw * 64;
    const int qr = lane >> 2, qc = lane & 3;
    const int grp = lane >> 3, lr = lane & 7;

    float acc[2][8][4];
#pragma unroll
    for (int mh = 0; mh < 2; mh++)
#pragma unroll
        for (int j = 0; j < 8; j++)
#pragma unroll
            for (int q = 0; q < 4; q++) acc[mh][j][q] = 0.f;

#pragma unroll
    for (int k = 0; k < 7; k++) {
        uint32_t ah[2][4], al[2][4];
#pragma unroll
        for (int mh = 0; mh < 2; mh++) {
            uint32_t aaddr = smb + O_AHI + (uint32_t)((m0 + 16 * mh + lr + ((grp & 1) << 3)) * 240
                           + k * 32 + ((grp >> 1) << 4));
            ldsm4(ah[mh], aaddr);
            ldsm4(al[mh], aaddr + 30720u);
        }
#pragma unroll
        for (int pq = 0; pq < 4; pq++) {
            uint32_t addr = smb + O_BHI + (uint32_t)((n0 + pq * 16 + lr + (grp >> 1) * 8) * 240
                          + k * 32 + (grp & 1) * 16);
            uint32_t bh[4], bl[4];
            ldsm4(bh, addr);
            ldsm4(bl, addr + 30720u);
#pragma unroll
            for (int mh = 0; mh < 2; mh++)
#pragma unroll
                for (int jj = 0; jj < 2; jj++) {
                    int j = pq * 2 + jj;
                    mma16816(acc[mh][j], ah[mh], &bh[2 * jj]);
                    mma16816(acc[mh][j], al[mh], &bh[2 * jj]);
                    mma16816(acc[mh][j], ah[mh], &bl[2 * jj]);
                }
        }
    }

#pragma unroll
    for (int mh = 0; mh < 2; mh++) {
        int ra = b0 + m0 + 16 * mh + qr;
        int rb2 = ra + 8;
#pragma unroll
        for (int j = 0; j < 8; j++) {
            int c = v0 + n0 + j * 8 + 2 * qc;
            float2 rb = *(const float2*)(R_b + c);
            float2 o0 = make_float2(acc[mh][j][0] + rb.x, acc[mh][j][1] + rb.y);
            float2 o1 = make_float2(acc[mh][j][2] + rb.x, acc[mh][j][3] + rb.y);
            *(float2*)(out + (long)ra * V_ + c) = o0;
            *(float2*)(out + (long)rb2 * V_ + c) = o1;
        }
    }
}

// ============================================================
extern "C" void kernel_launch(void* const* d_in, const int* in_sizes, int n_in,
                              void* d_out, int out_size) {
    const float* in_data = (const float*)d_in[0];
    const float* f       = (const float*)d_in[1];
    const float* h0      = (const float*)d_in[2];
    const float* w_mem   = (const float*)d_in[3];
    const float* U_w     = (const float*)d_in[4];
    const float* V_w     = (const float*)d_in[5];
    const float* W_w     = (const float*)d_in[6];
    const float* a_dm    = (const float*)d_in[7];
    const float* H_w     = (const float*)d_in[8];
    const float* H_b     = (const float*)d_in[9];
    const float* R_w     = (const float*)d_in[10];
    const float* R_b     = (const float*)d_in[11];
    const float* a_out   = (const float*)d_in[12];
    float* out = (float*)d_out;

    cudaFuncSetAttribute(scan_mma_kernel, cudaFuncAttributeMaxDynamicSharedMemorySize,
                         SCAN_SMEM);
    cudaFuncSetAttribute(out_mma_kernel, cudaFuncAttributeMaxDynamicSharedMemorySize,
                         OUT_SMEM);

    scan_mma_kernel<<<B_ / NB, NTH, SCAN_SMEM>>>(U_w, V_w, W_w, w_mem, h0, a_dm,
                                                 in_data, f, H_w, H_b, a_out);
    const int conv_total = V_ * 60 + B_ * 60;
    convert_kernel<<<(conv_total + 255) / 256, 256>>>(R_w);
    dim3 g4(V_ / 128, B_ / 128);
    out_mma_kernel<<<g4, 256, OUT_SMEM>>>(R_b, out);
}